// round 3
// baseline (speedup 1.0000x reference)
#include <cuda_runtime.h>
#include <math.h>
#include <stdint.h>

#define NN 50000
#define NE 800000
#define NBLK ((NN + 1023) / 1024)   // 49 scan blocks

// ---------------- scratch (static device globals; no allocation) -------------
__device__ int   g_cnt[NN];
__device__ int   g_rowptr[NN + 1];
__device__ int   g_cursor[NN];
__device__ int   g_colsrc[NE];
__device__ int   g_bsum[64];
__device__ float g_dinv[NN];
__device__ float g_h32 [(size_t)NN * 32];
__device__ float g_h64 [(size_t)NN * 64];
__device__ float g_h128[(size_t)NN * 128];
__device__ float g_p128[(size_t)NN * 128];
__device__ float g_h256[(size_t)NN * 256];
__device__ float g_p256[(size_t)NN * 256];
__device__ float g_h512[(size_t)NN * 512];
__device__ float g_t64 [(size_t)NN * 64];
__device__ float g_p64 [(size_t)NN * 64];

// ---------------- degree / CSR build -----------------------------------------
__global__ void k_zero_cnt() {
    int i = blockIdx.x * blockDim.x + threadIdx.x;
    if (i < NN) g_cnt[i] = 0;
}

__global__ void k_count(const int* __restrict__ ei) {
    int e = blockIdx.x * blockDim.x + threadIdx.x;
    if (e < NE) {
        int dst = ei[NE + e];
        if ((unsigned)dst < NN) atomicAdd(&g_cnt[dst], 1);
    }
}

__global__ void k_dinv() {
    int i = blockIdx.x * blockDim.x + threadIdx.x;
    if (i < NN) g_dinv[i] = rsqrtf((float)g_cnt[i] + 1.0f);
}

__global__ void k_scan1() {
    __shared__ int sh[1024];
    int tid = threadIdx.x;
    int i = blockIdx.x * 1024 + tid;
    int v = (i < NN) ? g_cnt[i] : 0;
    sh[tid] = v;
    __syncthreads();
    for (int off = 1; off < 1024; off <<= 1) {
        int t = (tid >= off) ? sh[tid - off] : 0;
        __syncthreads();
        sh[tid] += t;
        __syncthreads();
    }
    if (i < NN) g_rowptr[i] = sh[tid] - v;
    if (tid == 1023) g_bsum[blockIdx.x] = sh[1023];
}

__global__ void k_scan2() {
    __shared__ int sh[64];
    int tid = threadIdx.x;
    int v = (tid < NBLK) ? g_bsum[tid] : 0;
    sh[tid] = v;
    __syncthreads();
    for (int off = 1; off < 64; off <<= 1) {
        int t = (tid >= off) ? sh[tid - off] : 0;
        __syncthreads();
        sh[tid] += t;
        __syncthreads();
    }
    g_bsum[tid] = sh[tid] - v;
}

__global__ void k_scan3() {
    int i = blockIdx.x * blockDim.x + threadIdx.x;
    if (i < NN) {
        int r = g_rowptr[i] + g_bsum[i >> 10];
        g_rowptr[i] = r;
        g_cursor[i] = r;
    }
    if (i == 0) g_rowptr[NN] = NE;
}

__global__ void k_scatter(const int* __restrict__ ei) {
    int e = blockIdx.x * blockDim.x + threadIdx.x;
    if (e < NE) {
        int dst = ei[NE + e];
        int src = ei[e];
        if ((unsigned)dst < NN && (unsigned)src < NN) {
            int pos = atomicAdd(&g_cursor[dst], 1);
            if ((unsigned)pos < NE) g_colsrc[pos] = src;
        }
    }
}

// ---------------- small SIMT GEMM (MLP layers 1-2, tiny K) --------------------
__global__ __launch_bounds__(256)
void k_gemm(const float* __restrict__ A, const float* __restrict__ W,
            const float* __restrict__ bias, float* __restrict__ C,
            int M, int K, int Ntrue, int Npad, int relu) {
    constexpr int BM = 64, BN = 64, BK = 16;
    __shared__ float sA[BK][BM + 1];
    __shared__ float sB[BK][BN];
    int tid = threadIdx.x;
    int tx = tid & 15;
    int ty = tid >> 4;
    int bm0 = blockIdx.x * BM;
    int bn0 = blockIdx.y * BN;

    float acc[4][4];
#pragma unroll
    for (int i = 0; i < 4; i++)
#pragma unroll
        for (int j = 0; j < 4; j++) acc[i][j] = 0.f;

    for (int k0 = 0; k0 < K; k0 += BK) {
#pragma unroll
        for (int i = 0; i < 4; i++) {
            int idx = tid + i * 256;
            int r = idx >> 4, kk = idx & 15;
            int gr = bm0 + r, gk = k0 + kk;
            sA[kk][r] = (gr < M && gk < K) ? A[(size_t)gr * K + gk] : 0.f;
        }
#pragma unroll
        for (int i = 0; i < 4; i++) {
            int idx = tid + i * 256;
            int kk = idx >> 6, nn = idx & 63;
            int gk = k0 + kk, gn = bn0 + nn;
            sB[kk][nn] = (gk < K && gn < Ntrue) ? W[(size_t)gk * Ntrue + gn] : 0.f;
        }
        __syncthreads();
#pragma unroll
        for (int kk = 0; kk < BK; kk++) {
            float a0 = sA[kk][ty * 4 + 0];
            float a1 = sA[kk][ty * 4 + 1];
            float a2 = sA[kk][ty * 4 + 2];
            float a3 = sA[kk][ty * 4 + 3];
            float4 b = *(const float4*)&sB[kk][tx * 4];
            acc[0][0] += a0 * b.x; acc[0][1] += a0 * b.y; acc[0][2] += a0 * b.z; acc[0][3] += a0 * b.w;
            acc[1][0] += a1 * b.x; acc[1][1] += a1 * b.y; acc[1][2] += a1 * b.z; acc[1][3] += a1 * b.w;
            acc[2][0] += a2 * b.x; acc[2][1] += a2 * b.y; acc[2][2] += a2 * b.z; acc[2][3] += a2 * b.w;
            acc[3][0] += a3 * b.x; acc[3][1] += a3 * b.y; acc[3][2] += a3 * b.z; acc[3][3] += a3 * b.w;
        }
        __syncthreads();
    }
#pragma unroll
    for (int i = 0; i < 4; i++) {
        int row = bm0 + ty * 4 + i;
        if (row >= M) continue;
#pragma unroll
        for (int j = 0; j < 4; j++) {
            int col = bn0 + tx * 4 + j;
            if (col >= Npad) continue;
            float v = 0.f;
            if (col < Ntrue) {
                v = acc[i][j];
                if (bias) v += bias[col];
                if (relu) v = fmaxf(v, 0.f);
            }
            C[(size_t)row * Npad + col] = v;
        }
    }
}

// ---------------- 3xTF32 tensor-core GEMM ------------------------------------
// C[M,Npad] = act(A[M,K] @ W[K,Ntrue] + bias). Requires K % 32 == 0, Npad % 64 == 0.
__device__ __forceinline__ uint32_t f2tf(float x) {
    uint32_t r;
    asm("cvt.rna.tf32.f32 %0, %1;" : "=r"(r) : "f"(x));
    return r;
}

__device__ __forceinline__ void mma8(float c[4], const uint32_t a[4], const uint32_t b[2]) {
    asm("mma.sync.aligned.m16n8k8.row.col.f32.tf32.tf32.f32 "
        "{%0,%1,%2,%3},{%4,%5,%6,%7},{%8,%9},{%0,%1,%2,%3};"
        : "+f"(c[0]), "+f"(c[1]), "+f"(c[2]), "+f"(c[3])
        : "r"(a[0]), "r"(a[1]), "r"(a[2]), "r"(a[3]), "r"(b[0]), "r"(b[1]));
}

__global__ __launch_bounds__(256)
void k_gemm_tf32(const float* __restrict__ A, const float* __restrict__ W,
                 const float* __restrict__ bias, float* __restrict__ C,
                 int M, int K, int Ntrue, int Npad, int relu) {
    constexpr int BM = 128, BN = 64, BK = 32;
    constexpr int ASTR = 36;   // (4r+k)%32 conflict-free fragment reads
    constexpr int BSTR = 72;   // (8k+n)%32 conflict-free fragment reads
    __shared__ float sA[BM * ASTR];
    __shared__ float sB[BK * BSTR];

    int tid = threadIdx.x;
    int lane = tid & 31;
    int wid = tid >> 5;
    int wm = (wid & 3) * 32;       // warp row offset in tile
    int wn = (wid >> 2) * 32;      // warp col offset in tile
    int bm0 = blockIdx.x * BM;
    int bn0 = blockIdx.y * BN;

    float c[2][4][4];
#pragma unroll
    for (int mi = 0; mi < 2; mi++)
#pragma unroll
        for (int nj = 0; nj < 4; nj++)
#pragma unroll
            for (int r = 0; r < 4; r++) c[mi][nj][r] = 0.f;

    for (int k0 = 0; k0 < K; k0 += BK) {
        // load A tile 128x32 (float4 per thread x4)
        {
            int r = tid >> 3, c4 = (tid & 7) * 4;
#pragma unroll
            for (int i = 0; i < 4; i++, r += 32) {
                int gr = bm0 + r;
                float4 v = make_float4(0.f, 0.f, 0.f, 0.f);
                if (gr < M) v = *(const float4*)&A[(size_t)gr * K + k0 + c4];
                *(float4*)&sA[r * ASTR + c4] = v;
            }
        }
        // load W tile 32x64 (scalar, guarded against Ntrue)
        {
            int r = tid >> 4, c4 = (tid & 15) * 4;
#pragma unroll
            for (int i = 0; i < 2; i++, r += 16) {
                int gk = k0 + r;
#pragma unroll
                for (int j = 0; j < 4; j++) {
                    int gn = bn0 + c4 + j;
                    sB[r * BSTR + c4 + j] =
                        (gn < Ntrue) ? W[(size_t)gk * Ntrue + gn] : 0.f;
                }
            }
        }
        __syncthreads();

#pragma unroll
        for (int k8 = 0; k8 < 4; k8++) {
            int kb = k8 * 8;
            uint32_t ahi[2][4], alo[2][4], bhi[4][2], blo[4][2];
            int ar = wm + (lane >> 2);
            int ac = kb + (lane & 3);
#pragma unroll
            for (int mi = 0; mi < 2; mi++) {
                float f0 = sA[(ar + mi * 16) * ASTR + ac];
                float f1 = sA[(ar + mi * 16 + 8) * ASTR + ac];
                float f2 = sA[(ar + mi * 16) * ASTR + ac + 4];
                float f3 = sA[(ar + mi * 16 + 8) * ASTR + ac + 4];
                ahi[mi][0] = f2tf(f0); alo[mi][0] = f2tf(f0 - __uint_as_float(ahi[mi][0]));
                ahi[mi][1] = f2tf(f1); alo[mi][1] = f2tf(f1 - __uint_as_float(ahi[mi][1]));
                ahi[mi][2] = f2tf(f2); alo[mi][2] = f2tf(f2 - __uint_as_float(ahi[mi][2]));
                ahi[mi][3] = f2tf(f3); alo[mi][3] = f2tf(f3 - __uint_as_float(ahi[mi][3]));
            }
            int bk = kb + (lane & 3);
            int bn = wn + (lane >> 2);
#pragma unroll
            for (int nj = 0; nj < 4; nj++) {
                float g0 = sB[bk * BSTR + bn + nj * 8];
                float g1 = sB[(bk + 4) * BSTR + bn + nj * 8];
                bhi[nj][0] = f2tf(g0); blo[nj][0] = f2tf(g0 - __uint_as_float(bhi[nj][0]));
                bhi[nj][1] = f2tf(g1); blo[nj][1] = f2tf(g1 - __uint_as_float(bhi[nj][1]));
            }
#pragma unroll
            for (int mi = 0; mi < 2; mi++)
#pragma unroll
                for (int nj = 0; nj < 4; nj++) {
                    mma8(c[mi][nj], alo[mi], bhi[nj]);
                    mma8(c[mi][nj], ahi[mi], blo[nj]);
                    mma8(c[mi][nj], ahi[mi], bhi[nj]);
                }
        }
        __syncthreads();
    }

    // epilogue
#pragma unroll
    for (int mi = 0; mi < 2; mi++) {
#pragma unroll
        for (int nj = 0; nj < 4; nj++) {
#pragma unroll
            for (int r = 0; r < 4; r++) {
                int row = bm0 + wm + mi * 16 + (lane >> 2) + ((r >= 2) ? 8 : 0);
                int col = bn0 + wn + nj * 8 + (lane & 3) * 2 + (r & 1);
                if (row >= M || col >= Npad) continue;
                float v = 0.f;
                if (col < Ntrue) {
                    v = c[mi][nj][r];
                    if (bias) v += bias[col];
                    if (relu) v = fmaxf(v, 0.f);
                }
                C[(size_t)row * Npad + col] = v;
            }
        }
    }
}

// ---------------- GCN propagation: p = A_norm h + dinv^2 * h -------------------
template <int C4>
__global__ void k_agg4(const float* __restrict__ h, float* __restrict__ p) {
    int v = blockIdx.x * 8 + (threadIdx.x >> 5);
    if (v >= NN) return;
    int lane = threadIdx.x & 31;
    constexpr int F = C4 * 128;
    float dv = g_dinv[v];
    const float4* hv = (const float4*)(h + (size_t)v * F);
    float4 acc[C4];
    float s2 = dv * dv;
#pragma unroll
    for (int i = 0; i < C4; i++) {
        float4 t = hv[lane + i * 32];
        acc[i] = make_float4(t.x * s2, t.y * s2, t.z * s2, t.w * s2);
    }
    int e = g_rowptr[v], end = g_rowptr[v + 1];
    for (; e < end; e++) {
        int s = g_colsrc[e];
        if ((unsigned)s >= NN) continue;
        float nrm = dv * g_dinv[s];
        const float4* hs = (const float4*)(h + (size_t)s * F);
#pragma unroll
        for (int i = 0; i < C4; i++) {
            float4 t = hs[lane + i * 32];
            acc[i].x += nrm * t.x; acc[i].y += nrm * t.y;
            acc[i].z += nrm * t.z; acc[i].w += nrm * t.w;
        }
    }
    float4* pv = (float4*)(p + (size_t)v * F);
#pragma unroll
    for (int i = 0; i < C4; i++) pv[lane + i * 32] = acc[i];
}

__global__ void k_agg_f2(const float* __restrict__ h, float* __restrict__ p) {
    int v = blockIdx.x * 8 + (threadIdx.x >> 5);
    if (v >= NN) return;
    int lane = threadIdx.x & 31;
    float dv = g_dinv[v];
    float2 a = ((const float2*)(h + (size_t)v * 64))[lane];
    float s2 = dv * dv;
    a.x *= s2; a.y *= s2;
    int e = g_rowptr[v], end = g_rowptr[v + 1];
    for (; e < end; e++) {
        int s = g_colsrc[e];
        if ((unsigned)s >= NN) continue;
        float nrm = dv * g_dinv[s];
        float2 t = ((const float2*)(h + (size_t)s * 64))[lane];
        a.x += nrm * t.x; a.y += nrm * t.y;
    }
    ((float2*)(p + (size_t)v * 64))[lane] = a;
}

// ---------------- softmax over 50 logits (+ final bias) ------------------------
__global__ void k_softmax(const float* __restrict__ p, const float* __restrict__ b,
                          float* __restrict__ out) {
    int v = blockIdx.x * 8 + (threadIdx.x >> 5);
    if (v >= NN) return;
    int lane = threadIdx.x & 31;
    const float* pv = p + (size_t)v * 64;
    float v0 = pv[lane] + b[lane];
    bool has1 = (lane + 32) < 50;
    float v1 = has1 ? (pv[lane + 32] + b[lane + 32]) : -1e30f;
    float m = fmaxf(v0, v1);
#pragma unroll
    for (int off = 16; off >= 1; off >>= 1)
        m = fmaxf(m, __shfl_xor_sync(0xffffffffu, m, off));
    float e0 = __expf(v0 - m);
    float e1 = has1 ? __expf(v1 - m) : 0.f;
    float s = e0 + e1;
#pragma unroll
    for (int off = 16; off >= 1; off >>= 1)
        s += __shfl_xor_sync(0xffffffffu, s, off);
    float inv = 1.0f / s;
    out[(size_t)v * 50 + lane] = e0 * inv;
    if (has1) out[(size_t)v * 50 + lane + 32] = e1 * inv;
}

// ---------------- launch ------------------------------------------------------
static inline void* sym(const void* s) {
    void* p = nullptr;
    cudaGetSymbolAddress(&p, s);
    return p;
}

extern "C" void kernel_launch(void* const* d_in, const int* in_sizes, int n_in,
                              void* d_out, int out_size) {
    const float* x   = (const float*)d_in[0];
    const int*   ei  = (const int*)d_in[1];
    const float* w1  = (const float*)d_in[2];
    const float* b1  = (const float*)d_in[3];
    const float* w2  = (const float*)d_in[4];
    const float* b2  = (const float*)d_in[5];
    const float* w3  = (const float*)d_in[6];
    const float* b3  = (const float*)d_in[7];
    const float* g1w = (const float*)d_in[8];
    const float* g1b = (const float*)d_in[9];
    const float* g2w = (const float*)d_in[10];
    const float* g2b = (const float*)d_in[11];
    const float* g3w = (const float*)d_in[12];
    const float* g3b = (const float*)d_in[13];
    float* out = (float*)d_out;

    float* h32  = (float*)sym(g_h32);
    float* h64  = (float*)sym(g_h64);
    float* h128 = (float*)sym(g_h128);
    float* p128 = (float*)sym(g_p128);
    float* h256 = (float*)sym(g_h256);
    float* p256 = (float*)sym(g_p256);
    float* h512 = (float*)sym(g_h512);
    float* t64  = (float*)sym(g_t64);
    float* p64  = (float*)sym(g_p64);

    // degree + CSR
    k_zero_cnt<<<(NN + 255) / 256, 256>>>();
    k_count<<<(NE + 255) / 256, 256>>>(ei);
    k_dinv<<<(NN + 255) / 256, 256>>>();
    k_scan1<<<NBLK, 1024>>>();
    k_scan2<<<1, 64>>>();
    k_scan3<<<(NN + 255) / 256, 256>>>();
    k_scatter<<<(NE + 255) / 256, 256>>>(ei);

    auto grid64  = [](int M, int Np) { return dim3((M + 63) / 64, (Np + 63) / 64); };
    auto grid128 = [](int M, int Np) { return dim3((M + 127) / 128, (Np + 63) / 64); };

    // MLP (small K -> SIMT; layer 3 -> tensor cores)
    k_gemm<<<grid64(NN, 32), 256>>>(x,   w1, b1, h32, NN, 3,  32, 32, 1);
    k_gemm<<<grid64(NN, 64), 256>>>(h32, w2, b2, h64, NN, 32, 64, 64, 1);
    k_gemm_tf32<<<grid128(NN, 128), 256>>>(h64, w3, b3, h128, NN, 64, 128, 128, 1);

    // GCN1: propagate at 128, then 128->256 matmul + bias + relu
    k_agg4<1><<<(NN + 7) / 8, 256>>>(h128, p128);
    k_gemm_tf32<<<grid128(NN, 256), 256>>>(p128, g1w, g1b, h256, NN, 128, 256, 256, 1);

    // GCN2: propagate at 256, then 256->512
    k_agg4<2><<<(NN + 7) / 8, 256>>>(h256, p256);
    k_gemm_tf32<<<grid128(NN, 512), 256>>>(p256, g2w, g2b, h512, NN, 256, 512, 512, 1);

    // GCN3: matmul 512->50 (padded to 64, no bias) first, then propagate at 64
    k_gemm_tf32<<<grid128(NN, 64), 256>>>(h512, g3w, nullptr, t64, NN, 512, 50, 64, 0);
    k_agg_f2<<<(NN + 7) / 8, 256>>>(t64, p64);

    // softmax(p + g3b)
    k_softmax<<<(NN + 7) / 8, 256>>>(p64, g3b, out);
}

// round 5
// speedup vs baseline: 1.4388x; 1.4388x over previous
#include <cuda_runtime.h>
#include <cuda_bf16.h>
#include <math.h>
#include <stdint.h>

#define NN 50000
#define NE 800000
#define NBLK ((NN + 1023) / 1024)

// ---------------- scratch (static device globals; no allocation) -------------
__device__ int   g_cnt[NN];
__device__ int   g_rowptr[NN + 1];
__device__ int   g_cursor[NN];
__device__ int   g_colsrc[NE];
__device__ int   g_bsum[64];
__device__ float g_dinv[NN];
__device__ float g_h32 [(size_t)NN * 32];
__device__ float g_h64 [(size_t)NN * 64];
__device__ float g_h128[(size_t)NN * 128];
__device__ float g_p128[(size_t)NN * 128];
__device__ float g_h256[(size_t)NN * 256];
__device__ float g_p256[(size_t)NN * 256];
__device__ float g_h512[(size_t)NN * 512];
__device__ float g_t64 [(size_t)NN * 64];
__device__ float g_p64 [(size_t)NN * 64];

// pre-split bf16 weights (hi/lo)
__device__ __nv_bfloat16 g_w2h[32 * 64],    g_w2l[32 * 64];
__device__ __nv_bfloat16 g_w3h[64 * 128],   g_w3l[64 * 128];
__device__ __nv_bfloat16 g_g1h[128 * 256],  g_g1l[128 * 256];
__device__ __nv_bfloat16 g_g2h[256 * 512],  g_g2l[256 * 512];
__device__ __nv_bfloat16 g_g3h[512 * 50],   g_g3l[512 * 50];

// ---------------- degree / CSR build -----------------------------------------
__global__ void k_zero_cnt() {
    int i = blockIdx.x * blockDim.x + threadIdx.x;
    if (i < NN) g_cnt[i] = 0;
}
__global__ void k_count(const int* __restrict__ ei) {
    int e = blockIdx.x * blockDim.x + threadIdx.x;
    if (e < NE) {
        int dst = ei[NE + e];
        if ((unsigned)dst < NN) atomicAdd(&g_cnt[dst], 1);
    }
}
__global__ void k_dinv() {
    int i = blockIdx.x * blockDim.x + threadIdx.x;
    if (i < NN) g_dinv[i] = rsqrtf((float)g_cnt[i] + 1.0f);
}
__global__ void k_scan1() {
    __shared__ int sh[1024];
    int tid = threadIdx.x;
    int i = blockIdx.x * 1024 + tid;
    int v = (i < NN) ? g_cnt[i] : 0;
    sh[tid] = v;
    __syncthreads();
    for (int off = 1; off < 1024; off <<= 1) {
        int t = (tid >= off) ? sh[tid - off] : 0;
        __syncthreads();
        sh[tid] += t;
        __syncthreads();
    }
    if (i < NN) g_rowptr[i] = sh[tid] - v;
    if (tid == 1023) g_bsum[blockIdx.x] = sh[1023];
}
__global__ void k_scan2() {
    __shared__ int sh[64];
    int tid = threadIdx.x;
    int v = (tid < NBLK) ? g_bsum[tid] : 0;
    sh[tid] = v;
    __syncthreads();
    for (int off = 1; off < 64; off <<= 1) {
        int t = (tid >= off) ? sh[tid - off] : 0;
        __syncthreads();
        sh[tid] += t;
        __syncthreads();
    }
    g_bsum[tid] = sh[tid] - v;
}
__global__ void k_scan3() {
    int i = blockIdx.x * blockDim.x + threadIdx.x;
    if (i < NN) {
        int r = g_rowptr[i] + g_bsum[i >> 10];
        g_rowptr[i] = r;
        g_cursor[i] = r;
    }
    if (i == 0) g_rowptr[NN] = NE;
}
__global__ void k_scatter(const int* __restrict__ ei) {
    int e = blockIdx.x * blockDim.x + threadIdx.x;
    if (e < NE) {
        int dst = ei[NE + e];
        int src = ei[e];
        if ((unsigned)dst < NN && (unsigned)src < NN) {
            int pos = atomicAdd(&g_cursor[dst], 1);
            if ((unsigned)pos < NE) g_colsrc[pos] = src;
        }
    }
}

// ---------------- weight hi/lo pre-split --------------------------------------
__global__ void k_split(const float* __restrict__ src, __nv_bfloat16* __restrict__ hi,
                        __nv_bfloat16* __restrict__ lo, int n) {
    int i = blockIdx.x * blockDim.x + threadIdx.x;
    if (i < n) {
        float x = src[i];
        __nv_bfloat16 h = __float2bfloat16(x);
        hi[i] = h;
        lo[i] = __float2bfloat16(x - __bfloat162float(h));
    }
}

// ---------------- small SIMT GEMM (MLP layer 1 only, K=3) ---------------------
__global__ __launch_bounds__(256)
void k_gemm(const float* __restrict__ A, const float* __restrict__ W,
            const float* __restrict__ bias, float* __restrict__ C,
            int M, int K, int Ntrue, int Npad, int relu) {
    constexpr int BM = 64, BN = 64, BK = 16;
    __shared__ float sA[BK][BM + 1];
    __shared__ float sB[BK][BN];
    int tid = threadIdx.x;
    int tx = tid & 15;
    int ty = tid >> 4;
    int bm0 = blockIdx.x * BM;
    int bn0 = blockIdx.y * BN;

    float acc[4][4];
#pragma unroll
    for (int i = 0; i < 4; i++)
#pragma unroll
        for (int j = 0; j < 4; j++) acc[i][j] = 0.f;

    for (int k0 = 0; k0 < K; k0 += BK) {
#pragma unroll
        for (int i = 0; i < 4; i++) {
            int idx = tid + i * 256;
            int r = idx >> 4, kk = idx & 15;
            int gr = bm0 + r, gk = k0 + kk;
            sA[kk][r] = (gr < M && gk < K) ? A[(size_t)gr * K + gk] : 0.f;
        }
#pragma unroll
        for (int i = 0; i < 4; i++) {
            int idx = tid + i * 256;
            int kk = idx >> 6, nn = idx & 63;
            int gk = k0 + kk, gn = bn0 + nn;
            sB[kk][nn] = (gk < K && gn < Ntrue) ? W[(size_t)gk * Ntrue + gn] : 0.f;
        }
        __syncthreads();
#pragma unroll
        for (int kk = 0; kk < BK; kk++) {
            float a0 = sA[kk][ty * 4 + 0];
            float a1 = sA[kk][ty * 4 + 1];
            float a2 = sA[kk][ty * 4 + 2];
            float a3 = sA[kk][ty * 4 + 3];
            float4 b = *(const float4*)&sB[kk][tx * 4];
            acc[0][0] += a0 * b.x; acc[0][1] += a0 * b.y; acc[0][2] += a0 * b.z; acc[0][3] += a0 * b.w;
            acc[1][0] += a1 * b.x; acc[1][1] += a1 * b.y; acc[1][2] += a1 * b.z; acc[1][3] += a1 * b.w;
            acc[2][0] += a2 * b.x; acc[2][1] += a2 * b.y; acc[2][2] += a2 * b.z; acc[2][3] += a2 * b.w;
            acc[3][0] += a3 * b.x; acc[3][1] += a3 * b.y; acc[3][2] += a3 * b.z; acc[3][3] += a3 * b.w;
        }
        __syncthreads();
    }
#pragma unroll
    for (int i = 0; i < 4; i++) {
        int row = bm0 + ty * 4 + i;
        if (row >= M) continue;
#pragma unroll
        for (int j = 0; j < 4; j++) {
            int col = bn0 + tx * 4 + j;
            if (col >= Npad) continue;
            float v = 0.f;
            if (col < Ntrue) {
                v = acc[i][j];
                if (bias) v += bias[col];
                if (relu) v = fmaxf(v, 0.f);
            }
            C[(size_t)row * Npad + col] = v;
        }
    }
}

// ---------------- bf16x3 tensor-core GEMM -------------------------------------
// C[M,Npad] = act(A[M,K] @ W[K,Ntrue] + bias); K % 32 == 0.
// BM=128, BN=64 per CTA; 8 warps = 4Mx2N, warp tile 32x32.
// 3-product bf16 split: Ahi*Bhi + Alo*Bhi + Ahi*Blo, fp32 accumulate.

__device__ __forceinline__ uint32_t pack_bf2(float a, float b) {
    __nv_bfloat162 h = __floats2bfloat162_rn(a, b);
    return *(uint32_t*)&h;
}
__device__ __forceinline__ void split1(float x, float& hi, float& lo) {
    __nv_bfloat16 h = __float2bfloat16(x);
    hi = __bfloat162float(h);
    lo = x - hi;
}
__device__ __forceinline__ void mma16(float c[4], const uint32_t a[4], uint32_t b0, uint32_t b1) {
    asm("mma.sync.aligned.m16n8k16.row.col.f32.bf16.bf16.f32 "
        "{%0,%1,%2,%3},{%4,%5,%6,%7},{%8,%9},{%0,%1,%2,%3};"
        : "+f"(c[0]), "+f"(c[1]), "+f"(c[2]), "+f"(c[3])
        : "r"(a[0]), "r"(a[1]), "r"(a[2]), "r"(a[3]), "r"(b0), "r"(b1));
}

template <bool RELU, bool BIAS>
__global__ __launch_bounds__(256)
void k_gemm_bf16(const float* __restrict__ A,
                 const __nv_bfloat16* __restrict__ Whi,
                 const __nv_bfloat16* __restrict__ Wlo,
                 const float* __restrict__ bias, float* __restrict__ C,
                 int M, int K, int Ntrue, int Npad) {
    constexpr int BM = 128, BN = 64, BK = 32;
    constexpr int ASTR = 40;                 // halves per row (padded, conflict-free)
    constexpr int A_HALVES = BM * ASTR;      // 5120
    constexpr int B_HALVES = BN * ASTR;      // 2560
    constexpr int STAGE_H = 2 * A_HALVES + 2 * B_HALVES;   // 15360 halves = 30720 B
    constexpr int OFF_AHI = 0, OFF_ALO = A_HALVES;
    constexpr int OFF_BHI = 2 * A_HALVES, OFF_BLO = 2 * A_HALVES + B_HALVES;

    extern __shared__ __nv_bfloat16 sm[];

    int tid = threadIdx.x;
    int lane = tid & 31;
    int wid = tid >> 5;
    int wm = (wid & 3) * 32;
    int wn = (wid >> 2) * 32;
    int bm0 = blockIdx.x * BM;
    int bn0 = blockIdx.y * BN;

    float c[2][4][4];
#pragma unroll
    for (int mi = 0; mi < 2; mi++)
#pragma unroll
        for (int nj = 0; nj < 4; nj++)
#pragma unroll
            for (int r = 0; r < 4; r++) c[mi][nj][r] = 0.f;

    const int T = K / BK;

    // staging registers
    float4 va[4];
    float vbh[8], vbl[8];
    int arow = tid >> 1, ahalf = tid & 1;            // A: row, 16-float half
    int bk = tid >> 3, bng = tid & 7;                // B: k row, n-group of 8

    auto ldg_tile = [&](int kt) {
        int k0 = kt * BK;
        bool ok = (bm0 + arow) < M;
        const float4* ga = (const float4*)(A + (size_t)(bm0 + arow) * K + k0 + ahalf * 16);
#pragma unroll
        for (int i = 0; i < 4; i++)
            va[i] = ok ? ga[i] : make_float4(0.f, 0.f, 0.f, 0.f);
        int gk = k0 + bk;
#pragma unroll
        for (int j = 0; j < 8; j++) {
            int gn = bn0 + bng * 8 + j;
            bool bo = gn < Ntrue;
            vbh[j] = bo ? __bfloat162float(Whi[(size_t)gk * Ntrue + gn]) : 0.f;
            vbl[j] = bo ? __bfloat162float(Wlo[(size_t)gk * Ntrue + gn]) : 0.f;
        }
    };

    auto sts_tile = [&](int buf) {
        __nv_bfloat16* st = sm + buf * STAGE_H;
        uint32_t abase = (uint32_t)arow * ASTR + (uint32_t)ahalf * 16;
#pragma unroll
        for (int i = 0; i < 4; i++) {
            float h0, l0, h1, l1, h2, l2, h3, l3;
            split1(va[i].x, h0, l0); split1(va[i].y, h1, l1);
            split1(va[i].z, h2, l2); split1(va[i].w, h3, l3);
            uint32_t off = abase + i * 4;
            *(uint2*)(st + OFF_AHI + off) = make_uint2(pack_bf2(h0, h1), pack_bf2(h2, h3));
            *(uint2*)(st + OFF_ALO + off) = make_uint2(pack_bf2(l0, l1), pack_bf2(l2, l3));
        }
#pragma unroll
        for (int j = 0; j < 8; j++) {
            uint32_t off = (uint32_t)(bng * 8 + j) * ASTR + bk;
            st[OFF_BHI + off] = __float2bfloat16(vbh[j]);
            st[OFF_BLO + off] = __float2bfloat16(vbl[j]);
        }
    };

    auto compute = [&](int buf) {
        const __nv_bfloat16* st = sm + buf * STAGE_H;
        const __nv_bfloat16* pAh = st + OFF_AHI;
        const __nv_bfloat16* pAl = st + OFF_ALO;
        const __nv_bfloat16* pBh = st + OFF_BHI;
        const __nv_bfloat16* pBl = st + OFF_BLO;
#pragma unroll
        for (int ch = 0; ch < 2; ch++) {
            int kk = ch * 16 + (lane & 3) * 2;
            uint32_t ah[2][4], al[2][4];
            int ar = wm + (lane >> 2);
#pragma unroll
            for (int mi = 0; mi < 2; mi++) {
                int r0 = ar + mi * 16;
                ah[mi][0] = *(const uint32_t*)(pAh + r0 * ASTR + kk);
                ah[mi][1] = *(const uint32_t*)(pAh + (r0 + 8) * ASTR + kk);
                ah[mi][2] = *(const uint32_t*)(pAh + r0 * ASTR + kk + 8);
                ah[mi][3] = *(const uint32_t*)(pAh + (r0 + 8) * ASTR + kk + 8);
                al[mi][0] = *(const uint32_t*)(pAl + r0 * ASTR + kk);
                al[mi][1] = *(const uint32_t*)(pAl + (r0 + 8) * ASTR + kk);
                al[mi][2] = *(const uint32_t*)(pAl + r0 * ASTR + kk + 8);
                al[mi][3] = *(const uint32_t*)(pAl + (r0 + 8) * ASTR + kk + 8);
            }
            int bn_ = wn + (lane >> 2);
#pragma unroll
            for (int nj = 0; nj < 4; nj++) {
                int nr = bn_ + nj * 8;
                uint32_t bh0 = *(const uint32_t*)(pBh + nr * ASTR + kk);
                uint32_t bh1 = *(const uint32_t*)(pBh + nr * ASTR + kk + 8);
                uint32_t bl0 = *(const uint32_t*)(pBl + nr * ASTR + kk);
                uint32_t bl1 = *(const uint32_t*)(pBl + nr * ASTR + kk + 8);
#pragma unroll
                for (int mi = 0; mi < 2; mi++) {
                    mma16(c[mi][nj], al[mi], bh0, bh1);
                    mma16(c[mi][nj], ah[mi], bl0, bl1);
                    mma16(c[mi][nj], ah[mi], bh0, bh1);
                }
            }
        }
    };

    // pipeline
    ldg_tile(0);
    sts_tile(0);
    __syncthreads();
    for (int kt = 0; kt < T; kt++) {
        if (kt + 1 < T) ldg_tile(kt + 1);
        compute(kt & 1);
        if (kt + 1 < T) sts_tile((kt + 1) & 1);
        __syncthreads();
    }

    // epilogue: direct float2 stores
#pragma unroll
    for (int mi = 0; mi < 2; mi++) {
#pragma unroll
        for (int nj = 0; nj < 4; nj++) {
            int row0 = bm0 + wm + mi * 16 + (lane >> 2);
            int col = bn0 + wn + nj * 8 + (lane & 3) * 2;
            float v0 = c[mi][nj][0], v1 = c[mi][nj][1];
            float v2 = c[mi][nj][2], v3 = c[mi][nj][3];
            if (BIAS) {
                float bb0 = (col < Ntrue) ? bias[col] : 0.f;
                float bb1 = (col + 1 < Ntrue) ? bias[col + 1] : 0.f;
                v0 += bb0; v1 += bb1; v2 += bb0; v3 += bb1;
            }
            if (RELU) {
                v0 = fmaxf(v0, 0.f); v1 = fmaxf(v1, 0.f);
                v2 = fmaxf(v2, 0.f); v3 = fmaxf(v3, 0.f);
            }
            if (row0 < M)
                *(float2*)&C[(size_t)row0 * Npad + col] = make_float2(v0, v1);
            if (row0 + 8 < M)
                *(float2*)&C[(size_t)(row0 + 8) * Npad + col] = make_float2(v2, v3);
        }
    }
}

// ---------------- GCN propagation ---------------------------------------------
template <int C4>
__global__ void k_agg4(const float* __restrict__ h, float* __restrict__ p) {
    int v = blockIdx.x * 8 + (threadIdx.x >> 5);
    if (v >= NN) return;
    int lane = threadIdx.x & 31;
    constexpr int F = C4 * 128;
    float dv = g_dinv[v];
    const float4* hv = (const float4*)(h + (size_t)v * F);
    float4 acc[C4];
    float s2 = dv * dv;
#pragma unroll
    for (int i = 0; i < C4; i++) {
        float4 t = hv[lane + i * 32];
        acc[i] = make_float4(t.x * s2, t.y * s2, t.z * s2, t.w * s2);
    }
    int e = g_rowptr[v], end = g_rowptr[v + 1];
    for (; e < end; e++) {
        int s = g_colsrc[e];
        if ((unsigned)s >= NN) continue;
        float nrm = dv * g_dinv[s];
        const float4* hs = (const float4*)(h + (size_t)s * F);
#pragma unroll
        for (int i = 0; i < C4; i++) {
            float4 t = hs[lane + i * 32];
            acc[i].x += nrm * t.x; acc[i].y += nrm * t.y;
            acc[i].z += nrm * t.z; acc[i].w += nrm * t.w;
        }
    }
    float4* pv = (float4*)(p + (size_t)v * F);
#pragma unroll
    for (int i = 0; i < C4; i++) pv[lane + i * 32] = acc[i];
}

__global__ void k_agg_f2(const float* __restrict__ h, float* __restrict__ p) {
    int v = blockIdx.x * 8 + (threadIdx.x >> 5);
    if (v >= NN) return;
    int lane = threadIdx.x & 31;
    float dv = g_dinv[v];
    float2 a = ((const float2*)(h + (size_t)v * 64))[lane];
    float s2 = dv * dv;
    a.x *= s2; a.y *= s2;
    int e = g_rowptr[v], end = g_rowptr[v + 1];
    for (; e < end; e++) {
        int s = g_colsrc[e];
        if ((unsigned)s >= NN) continue;
        float nrm = dv * g_dinv[s];
        float2 t = ((const float2*)(h + (size_t)s * 64))[lane];
        a.x += nrm * t.x; a.y += nrm * t.y;
    }
    ((float2*)(p + (size_t)v * 64))[lane] = a;
}

// ---------------- softmax over 50 logits (+ final bias) ------------------------
__global__ void k_softmax(const float* __restrict__ p, const float* __restrict__ b,
                          float* __restrict__ out) {
    int v = blockIdx.x * 8 + (threadIdx.x >> 5);
    if (v >= NN) return;
    int lane = threadIdx.x & 31;
    const float* pv = p + (size_t)v * 64;
    float v0 = pv[lane] + b[lane];
    bool has1 = (lane + 32) < 50;
    float v1 = has1 ? (pv[lane + 32] + b[lane + 32]) : -1e30f;
    float m = fmaxf(v0, v1);
#pragma unroll
    for (int off = 16; off >= 1; off >>= 1)
        m = fmaxf(m, __shfl_xor_sync(0xffffffffu, m, off));
    float e0 = __expf(v0 - m);
    float e1 = has1 ? __expf(v1 - m) : 0.f;
    float s = e0 + e1;
#pragma unroll
    for (int off = 16; off >= 1; off >>= 1)
        s += __shfl_xor_sync(0xffffffffu, s, off);
    float inv = 1.0f / s;
    out[(size_t)v * 50 + lane] = e0 * inv;
    if (has1) out[(size_t)v * 50 + lane + 32] = e1 * inv;
}

// ---------------- launch ------------------------------------------------------
static inline void* sym(const void* s) {
    void* p = nullptr;
    cudaGetSymbolAddress(&p, s);
    return p;
}

extern "C" void kernel_launch(void* const* d_in, const int* in_sizes, int n_in,
                              void* d_out, int out_size) {
    const float* x   = (const float*)d_in[0];
    const int*   ei  = (const int*)d_in[1];
    const float* w1  = (const float*)d_in[2];
    const float* b1  = (const float*)d_in[3];
    const float* w2  = (const float*)d_in[4];
    const float* b2  = (const float*)d_in[5];
    const float* w3  = (const float*)d_in[6];
    const float* b3  = (const float*)d_in[7];
    const float* g1w = (const float*)d_in[8];
    const float* g1b = (const float*)d_in[9];
    const float* g2w = (const float*)d_in[10];
    const float* g2b = (const float*)d_in[11];
    const float* g3w = (const float*)d_in[12];
    const float* g3b = (const float*)d_in[13];
    float* out = (float*)d_out;

    float* h32  = (float*)sym(g_h32);
    float* h64  = (float*)sym(g_h64);
    float* h128 = (float*)sym(g_h128);
    float* p128 = (float*)sym(g_p128);
    float* h256 = (float*)sym(g_h256);
    float* p256 = (float*)sym(g_p256);
    float* h512 = (float*)sym(g_h512);
    float* t64  = (float*)sym(g_t64);
    float* p64  = (float*)sym(g_p64);

    __nv_bfloat16* w2h = (__nv_bfloat16*)sym(g_w2h);
    __nv_bfloat16* w2l = (__nv_bfloat16*)sym(g_w2l);
    __nv_bfloat16* w3h = (__nv_bfloat16*)sym(g_w3h);
    __nv_bfloat16* w3l = (__nv_bfloat16*)sym(g_w3l);
    __nv_bfloat16* g1h = (__nv_bfloat16*)sym(g_g1h);
    __nv_bfloat16* g1l = (__nv_bfloat16*)sym(g_g1l);
    __nv_bfloat16* g2h = (__nv_bfloat16*)sym(g_g2h);
    __nv_bfloat16* g2l = (__nv_bfloat16*)sym(g_g2l);
    __nv_bfloat16* g3h = (__nv_bfloat16*)sym(g_g3h);
    __nv_bfloat16* g3l = (__nv_bfloat16*)sym(g_g3l);

    const int dynsm = 2 * 30720;   // 61440 B double-buffered stage
    static int attr_done = 0;
    if (!attr_done) {
        cudaFuncSetAttribute(k_gemm_bf16<true, true>,
                             cudaFuncAttributeMaxDynamicSharedMemorySize, dynsm);
        cudaFuncSetAttribute(k_gemm_bf16<false, false>,
                             cudaFuncAttributeMaxDynamicSharedMemorySize, dynsm);
        attr_done = 1;
    }

    // degree + CSR
    k_zero_cnt<<<(NN + 255) / 256, 256>>>();
    k_count<<<(NE + 255) / 256, 256>>>(ei);
    k_dinv<<<(NN + 255) / 256, 256>>>();
    k_scan1<<<NBLK, 1024>>>();
    k_scan2<<<1, 64>>>();
    k_scan3<<<(NN + 255) / 256, 256>>>();
    k_scatter<<<(NE + 255) / 256, 256>>>(ei);

    // weight splits (independent; cheap)
    k_split<<<(32 * 64 + 255) / 256, 256>>>(w2, w2h, w2l, 32 * 64);
    k_split<<<(64 * 128 + 255) / 256, 256>>>(w3, w3h, w3l, 64 * 128);
    k_split<<<(128 * 256 + 255) / 256, 256>>>(g1w, g1h, g1l, 128 * 256);
    k_split<<<(256 * 512 + 255) / 256, 256>>>(g2w, g2h, g2l, 256 * 512);
    k_split<<<(512 * 50 + 255) / 256, 256>>>(g3w, g3h, g3l, 512 * 50);

    const int MB = (NN + 127) / 128;   // 391

    // MLP1 (K=3): SIMT
    k_gemm<<<dim3((NN + 63) / 64, 1), 256>>>(x, w1, b1, h32, NN, 3, 32, 32, 1);
    // MLP2 (32->64)
    k_gemm_bf16<true, true><<<dim3(MB, 1), 256, dynsm>>>(h32, w2h, w2l, b2, h64, NN, 32, 64, 64);
    // MLP3 (64->128)
    k_gemm_bf16<true, true><<<dim3(MB, 2), 256, dynsm>>>(h64, w3h, w3l, b3, h128, NN, 64, 128, 128);

    // GCN1: propagate at 128, then 128->256
    k_agg4<1><<<(NN + 7) / 8, 256>>>(h128, p128);
    k_gemm_bf16<true, true><<<dim3(MB, 4), 256, dynsm>>>(p128, g1h, g1l, g1b, h256, NN, 128, 256, 256);

    // GCN2: propagate at 256, then 256->512
    k_agg4<2><<<(NN + 7) / 8, 256>>>(h256, p256);
    k_gemm_bf16<true, true><<<dim3(MB, 8), 256, dynsm>>>(p256, g2h, g2l, g2b, h512, NN, 256, 512, 512);

    // GCN3: 512->50 (pad 64, bias deferred to softmax), then propagate at 64
    k_gemm_bf16<false, false><<<dim3(MB, 1), 256, dynsm>>>(h512, g3h, g3l, nullptr, t64, NN, 512, 50, 64);
    k_agg_f2<<<(NN + 7) / 8, 256>>>(t64, p64);

    // softmax(p + g3b)
    k_softmax<<<(NN + 7) / 8, 256>>>(p64, g3b, out);
}

// round 6
// speedup vs baseline: 1.9164x; 1.3319x over previous
#include <cuda_runtime.h>
#include <cuda_bf16.h>
#include <math.h>
#include <stdint.h>

#define NN 50000
#define NE 800000
#define NBLK ((NN + 1023) / 1024)

// ---------------- scratch (static device globals; no allocation) -------------
__device__ int   g_cnt[NN];
__device__ int   g_rowptr[NN + 1];
__device__ int   g_cursor[NN];
__device__ int   g_colsrc[NE];
__device__ int   g_bsum[64];
__device__ float g_dinv[NN];

// fp32 intermediates (aggregation inputs / final stage)
__device__ float g_h128[(size_t)NN * 128];
__device__ float g_h256[(size_t)NN * 256];
__device__ float g_t64 [(size_t)NN * 64];
__device__ float g_p64 [(size_t)NN * 64];

// pre-split bf16 activation planes (GEMM A inputs)
__device__ __align__(256) __nv_bfloat16 g_h32h [(size_t)NN * 32],  g_h32l [(size_t)NN * 32];
__device__ __align__(256) __nv_bfloat16 g_h64h [(size_t)NN * 64],  g_h64l [(size_t)NN * 64];
__device__ __align__(256) __nv_bfloat16 g_p128h[(size_t)NN * 128], g_p128l[(size_t)NN * 128];
__device__ __align__(256) __nv_bfloat16 g_p256h[(size_t)NN * 256], g_p256l[(size_t)NN * 256];
__device__ __align__(256) __nv_bfloat16 g_h512h[(size_t)NN * 512], g_h512l[(size_t)NN * 512];

// pre-split TRANSPOSED weight planes [Ntrue][K]
__device__ __align__(256) __nv_bfloat16 g_w2h[64 * 32],   g_w2l[64 * 32];
__device__ __align__(256) __nv_bfloat16 g_w3h[128 * 64],  g_w3l[128 * 64];
__device__ __align__(256) __nv_bfloat16 g_g1h[256 * 128], g_g1l[256 * 128];
__device__ __align__(256) __nv_bfloat16 g_g2h[512 * 256], g_g2l[512 * 256];
__device__ __align__(256) __nv_bfloat16 g_g3h[50 * 512],  g_g3l[50 * 512];

// ---------------- helpers ------------------------------------------------------
__device__ __forceinline__ void split1(float x, float& hi, float& lo) {
    __nv_bfloat16 h = __float2bfloat16(x);
    hi = __bfloat162float(h);
    lo = x - hi;
}
__device__ __forceinline__ void mma16(float c[4], const uint32_t a[4], uint32_t b0, uint32_t b1) {
    asm("mma.sync.aligned.m16n8k16.row.col.f32.bf16.bf16.f32 "
        "{%0,%1,%2,%3},{%4,%5,%6,%7},{%8,%9},{%0,%1,%2,%3};"
        : "+f"(c[0]), "+f"(c[1]), "+f"(c[2]), "+f"(c[3])
        : "r"(a[0]), "r"(a[1]), "r"(a[2]), "r"(a[3]), "r"(b0), "r"(b1));
}

// ---------------- degree / CSR build -----------------------------------------
__global__ void k_zero_cnt() {
    int i = blockIdx.x * blockDim.x + threadIdx.x;
    if (i < NN) g_cnt[i] = 0;
}
__global__ void k_count(const int* __restrict__ ei) {
    int e = blockIdx.x * blockDim.x + threadIdx.x;
    if (e < NE) {
        int dst = ei[NE + e];
        if ((unsigned)dst < NN) atomicAdd(&g_cnt[dst], 1);
    }
}
__global__ void k_dinv() {
    int i = blockIdx.x * blockDim.x + threadIdx.x;
    if (i < NN) g_dinv[i] = rsqrtf((float)g_cnt[i] + 1.0f);
}
__global__ void k_scan1() {
    __shared__ int sh[1024];
    int tid = threadIdx.x;
    int i = blockIdx.x * 1024 + tid;
    int v = (i < NN) ? g_cnt[i] : 0;
    sh[tid] = v;
    __syncthreads();
    for (int off = 1; off < 1024; off <<= 1) {
        int t = (tid >= off) ? sh[tid - off] : 0;
        __syncthreads();
        sh[tid] += t;
        __syncthreads();
    }
    if (i < NN) g_rowptr[i] = sh[tid] - v;
    if (tid == 1023) g_bsum[blockIdx.x] = sh[1023];
}
__global__ void k_scan2() {
    __shared__ int sh[64];
    int tid = threadIdx.x;
    int v = (tid < NBLK) ? g_bsum[tid] : 0;
    sh[tid] = v;
    __syncthreads();
    for (int off = 1; off < 64; off <<= 1) {
        int t = (tid >= off) ? sh[tid - off] : 0;
        __syncthreads();
        sh[tid] += t;
        __syncthreads();
    }
    g_bsum[tid] = sh[tid] - v;
}
__global__ void k_scan3() {
    int i = blockIdx.x * blockDim.x + threadIdx.x;
    if (i < NN) {
        int r = g_rowptr[i] + g_bsum[i >> 10];
        g_rowptr[i] = r;
        g_cursor[i] = r;
    }
    if (i == 0) g_rowptr[NN] = NE;
}
__global__ void k_scatter(const int* __restrict__ ei) {
    int e = blockIdx.x * blockDim.x + threadIdx.x;
    if (e < NE) {
        int dst = ei[NE + e];
        int src = ei[e];
        if ((unsigned)dst < NN && (unsigned)src < NN) {
            int pos = atomicAdd(&g_cursor[dst], 1);
            if ((unsigned)pos < NE) g_colsrc[pos] = src;
        }
    }
}

// ---------------- weight split + transpose: out [N][K] planes -----------------
__global__ void k_split_t(const float* __restrict__ src, __nv_bfloat16* __restrict__ hi,
                          __nv_bfloat16* __restrict__ lo, int K, int N) {
    int i = blockIdx.x * blockDim.x + threadIdx.x;
    if (i < K * N) {
        int k = i / N, n = i % N;
        float x = src[i];
        float h, l;
        split1(x, h, l);
        hi[(size_t)n * K + k] = __float2bfloat16(h);
        lo[(size_t)n * K + k] = __float2bfloat16(l);
    }
}

// ---------------- MLP layer 1 (K=3 -> 32), writes planes ----------------------
__global__ __launch_bounds__(256)
void k_mlp1(const float* __restrict__ x, const float* __restrict__ w,
            const float* __restrict__ b,
            __nv_bfloat16* __restrict__ hh, __nv_bfloat16* __restrict__ hl) {
    __shared__ float sw[96], sb[32];
    int tid = threadIdx.x;
    if (tid < 96) sw[tid] = w[tid];
    if (tid < 32) sb[tid] = b[tid];
    __syncthreads();
    int v = blockIdx.x * 256 + tid;
    if (v >= NN) return;
    float x0 = x[3 * v], x1 = x[3 * v + 1], x2 = x[3 * v + 2];
    __nv_bfloat162* ph = (__nv_bfloat162*)(hh + (size_t)v * 32);
    __nv_bfloat162* pl = (__nv_bfloat162*)(hl + (size_t)v * 32);
#pragma unroll
    for (int j = 0; j < 32; j += 2) {
        float h0 = fmaxf(x0 * sw[j] + x1 * sw[32 + j] + x2 * sw[64 + j] + sb[j], 0.f);
        float h1 = fmaxf(x0 * sw[j + 1] + x1 * sw[32 + j + 1] + x2 * sw[64 + j + 1] + sb[j + 1], 0.f);
        float a0, l0, a1, l1;
        split1(h0, a0, l0);
        split1(h1, a1, l1);
        ph[j >> 1] = __floats2bfloat162_rn(a0, a1);
        pl[j >> 1] = __floats2bfloat162_rn(l0, l1);
    }
}

// ---------------- bf16x3 tensor-core GEMM (plane inputs) ----------------------
// C = act(A @ W^T + bias); A planes [M][K], W planes transposed [Ntrue][K].
// BM=128, BN in {64,128}; 8 warps = 4M x 2N; K % 32 == 0.
template <int BN, bool RELU, bool BIAS, bool OUTP>
__global__ __launch_bounds__(256)
void k_gemm_bf(const __nv_bfloat16* __restrict__ Ahi, const __nv_bfloat16* __restrict__ Alo,
               const __nv_bfloat16* __restrict__ Whi, const __nv_bfloat16* __restrict__ Wlo,
               const float* __restrict__ bias,
               float* __restrict__ Cf,
               __nv_bfloat16* __restrict__ Chi, __nv_bfloat16* __restrict__ Clo,
               int M, int K, int Ntrue, int Npad) {
    constexpr int BM = 128, BK = 32, ASTR = 40;
    constexpr int A_H = BM * ASTR;
    constexpr int B_H = BN * ASTR;
    constexpr int STAGE = 2 * A_H + 2 * B_H;
    constexpr int OAH = 0, OAL = A_H, OBH = 2 * A_H, OBL = 2 * A_H + B_H;
    constexpr int NJ = (BN / 2) / 8;      // mma n-steps per warp
    constexpr int TPN = 256 / BN;         // threads per B n-row
    constexpr int KSEG = BK / TPN;        // k elems per thread (8 or 16)
    constexpr int NV = KSEG / 8;          // uint4 loads per plane

    extern __shared__ __nv_bfloat16 sm[];
    int tid = threadIdx.x, lane = tid & 31, wid = tid >> 5;
    int wm = (wid & 3) * 32, wn = (wid >> 2) * (BN / 2);
    int bm0 = blockIdx.x * BM, bn0 = blockIdx.y * BN;

    float c[2][NJ][4];
#pragma unroll
    for (int mi = 0; mi < 2; mi++)
#pragma unroll
        for (int nj = 0; nj < NJ; nj++)
#pragma unroll
            for (int r = 0; r < 4; r++) c[mi][nj][r] = 0.f;

    int arow = tid >> 1, ahalf = tid & 1;
    int brow = tid / TPN, bseg = tid % TPN;
    uint4 vah[2], valo[2], vbh[NV], vbl[NV];
    const uint4 z4 = make_uint4(0, 0, 0, 0);

    auto ldg = [&](int kt) {
        int k0 = kt * BK;
        bool ok = (bm0 + arow) < M;
        const uint4* pa = (const uint4*)(Ahi + (size_t)(bm0 + arow) * K + k0 + ahalf * 16);
        const uint4* pl = (const uint4*)(Alo + (size_t)(bm0 + arow) * K + k0 + ahalf * 16);
        vah[0] = ok ? pa[0] : z4;
        vah[1] = ok ? pa[1] : z4;
        valo[0] = ok ? pl[0] : z4;
        valo[1] = ok ? pl[1] : z4;
        int gn = bn0 + brow;
        bool bo = gn < Ntrue;
        const uint4* pb = (const uint4*)(Whi + (size_t)gn * K + k0 + bseg * KSEG);
        const uint4* pbl = (const uint4*)(Wlo + (size_t)gn * K + k0 + bseg * KSEG);
#pragma unroll
        for (int v = 0; v < NV; v++) {
            vbh[v] = bo ? pb[v] : z4;
            vbl[v] = bo ? pbl[v] : z4;
        }
    };

    auto sts = [&](int buf) {
        __nv_bfloat16* st = sm + buf * STAGE;
        uint32_t ao = (uint32_t)arow * ASTR + ahalf * 16;
        *(uint4*)(st + OAH + ao) = vah[0];
        *(uint4*)(st + OAH + ao + 8) = vah[1];
        *(uint4*)(st + OAL + ao) = valo[0];
        *(uint4*)(st + OAL + ao + 8) = valo[1];
        uint32_t bo_ = (uint32_t)brow * ASTR + bseg * KSEG;
#pragma unroll
        for (int v = 0; v < NV; v++) {
            *(uint4*)(st + OBH + bo_ + v * 8) = vbh[v];
            *(uint4*)(st + OBL + bo_ + v * 8) = vbl[v];
        }
    };

    auto comp = [&](int buf) {
        const __nv_bfloat16* st = sm + buf * STAGE;
#pragma unroll
        for (int ch = 0; ch < 2; ch++) {
            int kk = ch * 16 + (lane & 3) * 2;
            uint32_t ah[2][4], al[2][4];
            int ar = wm + (lane >> 2);
#pragma unroll
            for (int mi = 0; mi < 2; mi++) {
                int r0 = ar + mi * 16;
                ah[mi][0] = *(const uint32_t*)(st + OAH + r0 * ASTR + kk);
                ah[mi][1] = *(const uint32_t*)(st + OAH + (r0 + 8) * ASTR + kk);
                ah[mi][2] = *(const uint32_t*)(st + OAH + r0 * ASTR + kk + 8);
                ah[mi][3] = *(const uint32_t*)(st + OAH + (r0 + 8) * ASTR + kk + 8);
                al[mi][0] = *(const uint32_t*)(st + OAL + r0 * ASTR + kk);
                al[mi][1] = *(const uint32_t*)(st + OAL + (r0 + 8) * ASTR + kk);
                al[mi][2] = *(const uint32_t*)(st + OAL + r0 * ASTR + kk + 8);
                al[mi][3] = *(const uint32_t*)(st + OAL + (r0 + 8) * ASTR + kk + 8);
            }
            int nr0 = wn + (lane >> 2);
#pragma unroll
            for (int nj = 0; nj < NJ; nj++) {
                int nr = nr0 + nj * 8;
                uint32_t bh0 = *(const uint32_t*)(st + OBH + nr * ASTR + kk);
                uint32_t bh1 = *(const uint32_t*)(st + OBH + nr * ASTR + kk + 8);
                uint32_t bl0 = *(const uint32_t*)(st + OBL + nr * ASTR + kk);
                uint32_t bl1 = *(const uint32_t*)(st + OBL + nr * ASTR + kk + 8);
#pragma unroll
                for (int mi = 0; mi < 2; mi++) {
                    mma16(c[mi][nj], al[mi], bh0, bh1);
                    mma16(c[mi][nj], ah[mi], bl0, bl1);
                    mma16(c[mi][nj], ah[mi], bh0, bh1);
                }
            }
        }
    };

    const int T = K / BK;
    ldg(0);
    sts(0);
    __syncthreads();
    for (int kt = 0; kt < T; kt++) {
        if (kt + 1 < T) ldg(kt + 1);
        comp(kt & 1);
        if (kt + 1 < T) sts((kt + 1) & 1);
        __syncthreads();
    }

    // epilogue
#pragma unroll
    for (int mi = 0; mi < 2; mi++) {
#pragma unroll
        for (int nj = 0; nj < NJ; nj++) {
            int row0 = bm0 + wm + mi * 16 + (lane >> 2);
            int col = bn0 + wn + nj * 8 + (lane & 3) * 2;
            float v0 = c[mi][nj][0], v1 = c[mi][nj][1];
            float v2 = c[mi][nj][2], v3 = c[mi][nj][3];
            if (BIAS) {
                float bb0 = (col < Ntrue) ? bias[col] : 0.f;
                float bb1 = (col + 1 < Ntrue) ? bias[col + 1] : 0.f;
                v0 += bb0; v1 += bb1; v2 += bb0; v3 += bb1;
            }
            if (RELU) {
                v0 = fmaxf(v0, 0.f); v1 = fmaxf(v1, 0.f);
                v2 = fmaxf(v2, 0.f); v3 = fmaxf(v3, 0.f);
            }
            if (OUTP) {
                float h0, l0, h1, l1;
                if (row0 < M && col + 1 < Npad) {
                    split1(v0, h0, l0); split1(v1, h1, l1);
                    *(__nv_bfloat162*)(Chi + (size_t)row0 * Npad + col) = __floats2bfloat162_rn(h0, h1);
                    *(__nv_bfloat162*)(Clo + (size_t)row0 * Npad + col) = __floats2bfloat162_rn(l0, l1);
                }
                if (row0 + 8 < M && col + 1 < Npad) {
                    split1(v2, h0, l0); split1(v3, h1, l1);
                    *(__nv_bfloat162*)(Chi + (size_t)(row0 + 8) * Npad + col) = __floats2bfloat162_rn(h0, h1);
                    *(__nv_bfloat162*)(Clo + (size_t)(row0 + 8) * Npad + col) = __floats2bfloat162_rn(l0, l1);
                }
            } else {
                if (row0 < M && col + 1 < Npad)
                    *(float2*)&Cf[(size_t)row0 * Npad + col] = make_float2(v0, v1);
                if (row0 + 8 < M && col + 1 < Npad)
                    *(float2*)&Cf[(size_t)(row0 + 8) * Npad + col] = make_float2(v2, v3);
            }
        }
    }
}

// ---------------- GCN propagation: fp32 in, bf16 planes out --------------------
template <int C4>
__global__ void k_agg4p(const float* __restrict__ h,
                        __nv_bfloat16* __restrict__ phi, __nv_bfloat16* __restrict__ plo) {
    int v = blockIdx.x * 8 + (threadIdx.x >> 5);
    if (v >= NN) return;
    int lane = threadIdx.x & 31;
    constexpr int F = C4 * 128;
    float dv = g_dinv[v];
    const float4* hv = (const float4*)(h + (size_t)v * F);
    float4 acc[C4];
    float s2 = dv * dv;
#pragma unroll
    for (int i = 0; i < C4; i++) {
        float4 t = hv[lane + i * 32];
        acc[i] = make_float4(t.x * s2, t.y * s2, t.z * s2, t.w * s2);
    }
    int e = g_rowptr[v], end = g_rowptr[v + 1];
    for (; e < end; e++) {
        int s = g_colsrc[e];
        if ((unsigned)s >= NN) continue;
        float nrm = dv * g_dinv[s];
        const float4* hs = (const float4*)(h + (size_t)s * F);
#pragma unroll
        for (int i = 0; i < C4; i++) {
            float4 t = hs[lane + i * 32];
            acc[i].x += nrm * t.x; acc[i].y += nrm * t.y;
            acc[i].z += nrm * t.z; acc[i].w += nrm * t.w;
        }
    }
#pragma unroll
    for (int i = 0; i < C4; i++) {
        int base = 4 * (lane + i * 32);
        float hx, lx, hy, ly, hz, lz, hw, lw;
        split1(acc[i].x, hx, lx); split1(acc[i].y, hy, ly);
        split1(acc[i].z, hz, lz); split1(acc[i].w, hw, lw);
        *(__nv_bfloat162*)(phi + (size_t)v * F + base)     = __floats2bfloat162_rn(hx, hy);
        *(__nv_bfloat162*)(phi + (size_t)v * F + base + 2) = __floats2bfloat162_rn(hz, hw);
        *(__nv_bfloat162*)(plo + (size_t)v * F + base)     = __floats2bfloat162_rn(lx, ly);
        *(__nv_bfloat162*)(plo + (size_t)v * F + base + 2) = __floats2bfloat162_rn(lz, lw);
    }
}

// F = 64 fp32->fp32 variant (final layer)
__global__ void k_agg_f2(const float* __restrict__ h, float* __restrict__ p) {
    int v = blockIdx.x * 8 + (threadIdx.x >> 5);
    if (v >= NN) return;
    int lane = threadIdx.x & 31;
    float dv = g_dinv[v];
    float2 a = ((const float2*)(h + (size_t)v * 64))[lane];
    float s2 = dv * dv;
    a.x *= s2; a.y *= s2;
    int e = g_rowptr[v], end = g_rowptr[v + 1];
    for (; e < end; e++) {
        int s = g_colsrc[e];
        if ((unsigned)s >= NN) continue;
        float nrm = dv * g_dinv[s];
        float2 t = ((const float2*)(h + (size_t)s * 64))[lane];
        a.x += nrm * t.x; a.y += nrm * t.y;
    }
    ((float2*)(p + (size_t)v * 64))[lane] = a;
}

// ---------------- softmax over 50 logits (+ final bias) ------------------------
__global__ void k_softmax(const float* __restrict__ p, const float* __restrict__ b,
                          float* __restrict__ out) {
    int v = blockIdx.x * 8 + (threadIdx.x >> 5);
    if (v >= NN) return;
    int lane = threadIdx.x & 31;
    const float* pv = p + (size_t)v * 64;
    float v0 = pv[lane] + b[lane];
    bool has1 = (lane + 32) < 50;
    float v1 = has1 ? (pv[lane + 32] + b[lane + 32]) : -1e30f;
    float m = fmaxf(v0, v1);
#pragma unroll
    for (int off = 16; off >= 1; off >>= 1)
        m = fmaxf(m, __shfl_xor_sync(0xffffffffu, m, off));
    float e0 = __expf(v0 - m);
    float e1 = has1 ? __expf(v1 - m) : 0.f;
    float s = e0 + e1;
#pragma unroll
    for (int off = 16; off >= 1; off >>= 1)
        s += __shfl_xor_sync(0xffffffffu, s, off);
    float inv = 1.0f / s;
    out[(size_t)v * 50 + lane] = e0 * inv;
    if (has1) out[(size_t)v * 50 + lane + 32] = e1 * inv;
}

// ---------------- launch ------------------------------------------------------
static inline void* sym(const void* s) {
    void* p = nullptr;
    cudaGetSymbolAddress(&p, s);
    return p;
}

extern "C" void kernel_launch(void* const* d_in, const int* in_sizes, int n_in,
                              void* d_out, int out_size) {
    const float* x   = (const float*)d_in[0];
    const int*   ei  = (const int*)d_in[1];
    const float* w1  = (const float*)d_in[2];
    const float* b1  = (const float*)d_in[3];
    const float* w2  = (const float*)d_in[4];
    const float* b2  = (const float*)d_in[5];
    const float* w3  = (const float*)d_in[6];
    const float* b3  = (const float*)d_in[7];
    const float* g1w = (const float*)d_in[8];
    const float* g1b = (const float*)d_in[9];
    const float* g2w = (const float*)d_in[10];
    const float* g2b = (const float*)d_in[11];
    const float* g3w = (const float*)d_in[12];
    const float* g3b = (const float*)d_in[13];
    float* out = (float*)d_out;

    float* h128 = (float*)sym(g_h128);
    float* h256 = (float*)sym(g_h256);
    float* t64  = (float*)sym(g_t64);
    float* p64  = (float*)sym(g_p64);

    __nv_bfloat16* h32h = (__nv_bfloat16*)sym(g_h32h);
    __nv_bfloat16* h32l = (__nv_bfloat16*)sym(g_h32l);
    __nv_bfloat16* h64h = (__nv_bfloat16*)sym(g_h64h);
    __nv_bfloat16* h64l = (__nv_bfloat16*)sym(g_h64l);
    __nv_bfloat16* p128h = (__nv_bfloat16*)sym(g_p128h);
    __nv_bfloat16* p128l = (__nv_bfloat16*)sym(g_p128l);
    __nv_bfloat16* p256h = (__nv_bfloat16*)sym(g_p256h);
    __nv_bfloat16* p256l = (__nv_bfloat16*)sym(g_p256l);
    __nv_bfloat16* h512h = (__nv_bfloat16*)sym(g_h512h);
    __nv_bfloat16* h512l = (__nv_bfloat16*)sym(g_h512l);

    __nv_bfloat16* w2h = (__nv_bfloat16*)sym(g_w2h);
    __nv_bfloat16* w2l = (__nv_bfloat16*)sym(g_w2l);
    __nv_bfloat16* w3h = (__nv_bfloat16*)sym(g_w3h);
    __nv_bfloat16* w3l = (__nv_bfloat16*)sym(g_w3l);
    __nv_bfloat16* g1h = (__nv_bfloat16*)sym(g_g1h);
    __nv_bfloat16* g1l = (__nv_bfloat16*)sym(g_g1l);
    __nv_bfloat16* g2h = (__nv_bfloat16*)sym(g_g2h);
    __nv_bfloat16* g2l = (__nv_bfloat16*)sym(g_g2l);
    __nv_bfloat16* g3h = (__nv_bfloat16*)sym(g_g3h);
    __nv_bfloat16* g3l = (__nv_bfloat16*)sym(g_g3l);

    // dynamic smem: stage halves * 2B * 2 buffers
    const int dyn128 = (2 * 128 * 40 + 2 * 128 * 40) * 2 * 2;  // 81920
    const int dyn64  = (2 * 128 * 40 + 2 * 64 * 40) * 2 * 2;   // 61440
    static int attr_done = 0;
    if (!attr_done) {
        cudaFuncSetAttribute(k_gemm_bf<64, true, true, true>,
                             cudaFuncAttributeMaxDynamicSharedMemorySize, dyn64);
        cudaFuncSetAttribute(k_gemm_bf<128, true, true, false>,
                             cudaFuncAttributeMaxDynamicSharedMemorySize, dyn128);
        cudaFuncSetAttribute(k_gemm_bf<128, true, true, true>,
                             cudaFuncAttributeMaxDynamicSharedMemorySize, dyn128);
        cudaFuncSetAttribute(k_gemm_bf<64, false, false, false>,
                             cudaFuncAttributeMaxDynamicSharedMemorySize, dyn64);
        attr_done = 1;
    }

    // degree + CSR
    k_zero_cnt<<<(NN + 255) / 256, 256>>>();
    k_count<<<(NE + 255) / 256, 256>>>(ei);
    k_dinv<<<(NN + 255) / 256, 256>>>();
    k_scan1<<<NBLK, 1024>>>();
    k_scan2<<<1, 64>>>();
    k_scan3<<<(NN + 255) / 256, 256>>>();
    k_scatter<<<(NE + 255) / 256, 256>>>(ei);

    // weight split + transpose
    k_split_t<<<(32 * 64 + 255) / 256, 256>>>(w2, w2h, w2l, 32, 64);
    k_split_t<<<(64 * 128 + 255) / 256, 256>>>(w3, w3h, w3l, 64, 128);
    k_split_t<<<(128 * 256 + 255) / 256, 256>>>(g1w, g1h, g1l, 128, 256);
    k_split_t<<<(256 * 512 + 255) / 256, 256>>>(g2w, g2h, g2l, 256, 512);
    k_split_t<<<(512 * 50 + 255) / 256, 256>>>(g3w, g3h, g3l, 512, 50);

    const int MB = (NN + 127) / 128;   // 391

    // MLP1 (3->32): fused per-node, writes planes
    k_mlp1<<<(NN + 255) / 256, 256>>>(x, w1, b1, h32h, h32l);
    // MLP2 (32->64): planes out
    k_gemm_bf<64, true, true, true><<<dim3(MB, 1), 256, dyn64>>>(
        h32h, h32l, w2h, w2l, b2, nullptr, h64h, h64l, NN, 32, 64, 64);
    // MLP3 (64->128): fp32 out (feeds aggregation)
    k_gemm_bf<128, true, true, false><<<dim3(MB, 1), 256, dyn128>>>(
        h64h, h64l, w3h, w3l, b3, h128, nullptr, nullptr, NN, 64, 128, 128);

    // GCN1: propagate at 128 (planes out), then 128->256 fp32 out
    k_agg4p<1><<<(NN + 7) / 8, 256>>>(h128, p128h, p128l);
    k_gemm_bf<128, true, true, false><<<dim3(MB, 2), 256, dyn128>>>(
        p128h, p128l, g1h, g1l, g1b, h256, nullptr, nullptr, NN, 128, 256, 256);

    // GCN2: propagate at 256 (planes out), then 256->512 planes out
    k_agg4p<2><<<(NN + 7) / 8, 256>>>(h256, p256h, p256l);
    k_gemm_bf<128, true, true, true><<<dim3(MB, 4), 256, dyn128>>>(
        p256h, p256l, g2h, g2l, g2b, nullptr, h512h, h512l, NN, 256, 512, 512);

    // GCN3: 512->50 (pad 64, bias deferred), fp32 out, then propagate at 64
    k_gemm_bf<64, false, false, false><<<dim3(MB, 1), 256, dyn64>>>(
        h512h, h512l, g3h, g3l, nullptr, t64, nullptr, nullptr, NN, 512, 50, 64);
    k_agg_f2<<<(NN + 7) / 8, 256>>>(t64, p64);

    // softmax(p + g3b)
    k_softmax<<<(NN + 7) / 8, 256>>>(p64, g3b, out);
}

// round 7
// speedup vs baseline: 2.1137x; 1.1029x over previous
#include <cuda_runtime.h>
#include <cuda_bf16.h>
#include <math.h>
#include <stdint.h>

#define NN 50000
#define NE 800000
#define NBLK ((NN + 1023) / 1024)

// ---------------- scratch (static device globals; no allocation) -------------
__device__ int   g_cnt[NN];
__device__ int   g_rowptr[NN + 1];
__device__ int   g_cursor[NN];
__device__ int   g_colsrc[NE];
__device__ int   g_bsum[64];
__device__ float g_dinv[NN];

// fp32 intermediates (aggregation inputs / final stage)
__device__ float g_h128[(size_t)NN * 128];
__device__ float g_h256[(size_t)NN * 256];
__device__ float g_t64 [(size_t)NN * 64];
__device__ float g_p64 [(size_t)NN * 64];

// pre-split bf16 activation planes (GEMM A inputs)
__device__ __align__(256) __nv_bfloat16 g_h32h [(size_t)NN * 32],  g_h32l [(size_t)NN * 32];
__device__ __align__(256) __nv_bfloat16 g_h64h [(size_t)NN * 64],  g_h64l [(size_t)NN * 64];
__device__ __align__(256) __nv_bfloat16 g_p128h[(size_t)NN * 128], g_p128l[(size_t)NN * 128];
__device__ __align__(256) __nv_bfloat16 g_p256h[(size_t)NN * 256], g_p256l[(size_t)NN * 256];
__device__ __align__(256) __nv_bfloat16 g_h512h[(size_t)NN * 512], g_h512l[(size_t)NN * 512];

// pre-split TRANSPOSED weight planes [Ntrue][K]
__device__ __align__(256) __nv_bfloat16 g_w2h[64 * 32],   g_w2l[64 * 32];
__device__ __align__(256) __nv_bfloat16 g_w3h[128 * 64],  g_w3l[128 * 64];
__device__ __align__(256) __nv_bfloat16 g_g1h[256 * 128], g_g1l[256 * 128];
__device__ __align__(256) __nv_bfloat16 g_g2h[512 * 256], g_g2l[512 * 256];
__device__ __align__(256) __nv_bfloat16 g_g3h[50 * 512],  g_g3l[50 * 512];

// ---------------- helpers ------------------------------------------------------
__device__ __forceinline__ void split1(float x, float& hi, float& lo) {
    __nv_bfloat16 h = __float2bfloat16(x);
    hi = __bfloat162float(h);
    lo = x - hi;
}
__device__ __forceinline__ void mma16(float c[4], const uint32_t a[4], uint32_t b0, uint32_t b1) {
    asm("mma.sync.aligned.m16n8k16.row.col.f32.bf16.bf16.f32 "
        "{%0,%1,%2,%3},{%4,%5,%6,%7},{%8,%9},{%0,%1,%2,%3};"
        : "+f"(c[0]), "+f"(c[1]), "+f"(c[2]), "+f"(c[3])
        : "r"(a[0]), "r"(a[1]), "r"(a[2]), "r"(a[3]), "r"(b0), "r"(b1));
}
__device__ __forceinline__ void ldm_x4(uint32_t r[4], uint32_t saddr) {
    asm volatile("ldmatrix.sync.aligned.m8n8.x4.shared.b16 {%0,%1,%2,%3}, [%4];"
        : "=r"(r[0]), "=r"(r[1]), "=r"(r[2]), "=r"(r[3]) : "r"(saddr));
}
__device__ __forceinline__ uint32_t smem_u32(const void* p) {
    uint32_t a;
    asm("{ .reg .u64 t; cvta.to.shared.u64 t, %1; cvt.u32.u64 %0, t; }" : "=r"(a) : "l"(p));
    return a;
}

// ---------------- degree / CSR build -----------------------------------------
__global__ void k_zero_cnt() {
    int i = blockIdx.x * blockDim.x + threadIdx.x;
    if (i < NN) g_cnt[i] = 0;
}
__global__ void k_count(const int* __restrict__ ei) {
    int e = blockIdx.x * blockDim.x + threadIdx.x;
    if (e < NE) {
        int dst = ei[NE + e];
        if ((unsigned)dst < NN) atomicAdd(&g_cnt[dst], 1);
    }
}
__global__ void k_scan1() {   // + fused dinv
    __shared__ int sh[1024];
    int tid = threadIdx.x;
    int i = blockIdx.x * 1024 + tid;
    int v = (i < NN) ? g_cnt[i] : 0;
    if (i < NN) g_dinv[i] = rsqrtf((float)v + 1.0f);
    sh[tid] = v;
    __syncthreads();
    for (int off = 1; off < 1024; off <<= 1) {
        int t = (tid >= off) ? sh[tid - off] : 0;
        __syncthreads();
        sh[tid] += t;
        __syncthreads();
    }
    if (i < NN) g_rowptr[i] = sh[tid] - v;
    if (tid == 1023) g_bsum[blockIdx.x] = sh[1023];
}
__global__ void k_scan2() {
    __shared__ int sh[64];
    int tid = threadIdx.x;
    int v = (tid < NBLK) ? g_bsum[tid] : 0;
    sh[tid] = v;
    __syncthreads();
    for (int off = 1; off < 64; off <<= 1) {
        int t = (tid >= off) ? sh[tid - off] : 0;
        __syncthreads();
        sh[tid] += t;
        __syncthreads();
    }
    g_bsum[tid] = sh[tid] - v;
}
__global__ void k_scan3() {
    int i = blockIdx.x * blockDim.x + threadIdx.x;
    if (i < NN) {
        int r = g_rowptr[i] + g_bsum[i >> 10];
        g_rowptr[i] = r;
        g_cursor[i] = r;
    }
    if (i == 0) g_rowptr[NN] = NE;
}
__global__ void k_scatter(const int* __restrict__ ei) {
    int e = blockIdx.x * blockDim.x + threadIdx.x;
    if (e < NE) {
        int dst = ei[NE + e];
        int src = ei[e];
        if ((unsigned)dst < NN && (unsigned)src < NN) {
            int pos = atomicAdd(&g_cursor[dst], 1);
            if ((unsigned)pos < NE) g_colsrc[pos] = src;
        }
    }
}

// ---------------- weight split + transpose: out [N][K] planes -----------------
__global__ void k_split_t(const float* __restrict__ src, __nv_bfloat16* __restrict__ hi,
                          __nv_bfloat16* __restrict__ lo, int K, int N) {
    int i = blockIdx.x * blockDim.x + threadIdx.x;
    if (i < K * N) {
        int k = i / N, n = i % N;
        float x = src[i];
        float h, l;
        split1(x, h, l);
        hi[(size_t)n * K + k] = __float2bfloat16(h);
        lo[(size_t)n * K + k] = __float2bfloat16(l);
    }
}

// ---------------- MLP layer 1 (K=3 -> 32), writes planes ----------------------
__global__ __launch_bounds__(256)
void k_mlp1(const float* __restrict__ x, const float* __restrict__ w,
            const float* __restrict__ b,
            __nv_bfloat16* __restrict__ hh, __nv_bfloat16* __restrict__ hl) {
    __shared__ float sw[96], sb[32];
    int tid = threadIdx.x;
    if (tid < 96) sw[tid] = w[tid];
    if (tid < 32) sb[tid] = b[tid];
    __syncthreads();
    int v = blockIdx.x * 256 + tid;
    if (v >= NN) return;
    float x0 = x[3 * v], x1 = x[3 * v + 1], x2 = x[3 * v + 2];
    __nv_bfloat162* ph = (__nv_bfloat162*)(hh + (size_t)v * 32);
    __nv_bfloat162* pl = (__nv_bfloat162*)(hl + (size_t)v * 32);
#pragma unroll
    for (int j = 0; j < 32; j += 2) {
        float h0 = fmaxf(x0 * sw[j] + x1 * sw[32 + j] + x2 * sw[64 + j] + sb[j], 0.f);
        float h1 = fmaxf(x0 * sw[j + 1] + x1 * sw[32 + j + 1] + x2 * sw[64 + j + 1] + sb[j + 1], 0.f);
        float a0, l0, a1, l1;
        split1(h0, a0, l0);
        split1(h1, a1, l1);
        ph[j >> 1] = __floats2bfloat162_rn(a0, a1);
        pl[j >> 1] = __floats2bfloat162_rn(l0, l1);
    }
}

// ---------------- bf16x3 tensor-core GEMM (plane inputs, ldmatrix) ------------
template <int BN, bool RELU, bool BIAS, bool OUTP>
__global__ __launch_bounds__(256)
void k_gemm_bf(const __nv_bfloat16* __restrict__ Ahi, const __nv_bfloat16* __restrict__ Alo,
               const __nv_bfloat16* __restrict__ Whi, const __nv_bfloat16* __restrict__ Wlo,
               const float* __restrict__ bias,
               float* __restrict__ Cf,
               __nv_bfloat16* __restrict__ Chi, __nv_bfloat16* __restrict__ Clo,
               int M, int K, int Ntrue, int Npad) {
    constexpr int BM = 128, BK = 32, ASTR = 40;
    constexpr int A_H = BM * ASTR;
    constexpr int B_H = BN * ASTR;
    constexpr int STAGE = 2 * A_H + 2 * B_H;
    constexpr int OAH = 0, OAL = A_H, OBH = 2 * A_H, OBL = 2 * A_H + B_H;
    constexpr int NJ = (BN / 2) / 8;
    constexpr int TPN = 256 / BN;
    constexpr int KSEG = BK / TPN;
    constexpr int NV = KSEG / 8;

    extern __shared__ __nv_bfloat16 sm[];
    const uint32_t smb = smem_u32(sm);
    int tid = threadIdx.x, lane = tid & 31, wid = tid >> 5;
    int wm = (wid & 3) * 32, wn = (wid >> 2) * (BN / 2);
    int bm0 = blockIdx.x * BM, bn0 = blockIdx.y * BN;

    float c[2][NJ][4];
#pragma unroll
    for (int mi = 0; mi < 2; mi++)
#pragma unroll
        for (int nj = 0; nj < NJ; nj++)
#pragma unroll
            for (int r = 0; r < 4; r++) c[mi][nj][r] = 0.f;

    int arow = tid >> 1, ahalf = tid & 1;
    int brow = tid / TPN, bseg = tid % TPN;
    uint4 vah[2], valo[2], vbh[NV], vbl[NV];
    const uint4 z4 = make_uint4(0, 0, 0, 0);

    auto ldg = [&](int kt) {
        int k0 = kt * BK;
        bool ok = (bm0 + arow) < M;
        const uint4* pa = (const uint4*)(Ahi + (size_t)(bm0 + arow) * K + k0 + ahalf * 16);
        const uint4* pl = (const uint4*)(Alo + (size_t)(bm0 + arow) * K + k0 + ahalf * 16);
        vah[0] = ok ? pa[0] : z4;
        vah[1] = ok ? pa[1] : z4;
        valo[0] = ok ? pl[0] : z4;
        valo[1] = ok ? pl[1] : z4;
        int gn = bn0 + brow;
        bool bo = gn < Ntrue;
        const uint4* pb = (const uint4*)(Whi + (size_t)gn * K + k0 + bseg * KSEG);
        const uint4* pbl = (const uint4*)(Wlo + (size_t)gn * K + k0 + bseg * KSEG);
#pragma unroll
        for (int v = 0; v < NV; v++) {
            vbh[v] = bo ? pb[v] : z4;
            vbl[v] = bo ? pbl[v] : z4;
        }
    };

    auto sts = [&](int buf) {
        __nv_bfloat16* st = sm + buf * STAGE;
        uint32_t ao = (uint32_t)arow * ASTR + ahalf * 16;
        *(uint4*)(st + OAH + ao) = vah[0];
        *(uint4*)(st + OAH + ao + 8) = vah[1];
        *(uint4*)(st + OAL + ao) = valo[0];
        *(uint4*)(st + OAL + ao + 8) = valo[1];
        uint32_t bo_ = (uint32_t)brow * ASTR + bseg * KSEG;
#pragma unroll
        for (int v = 0; v < NV; v++) {
            *(uint4*)(st + OBH + bo_ + v * 8) = vbh[v];
            *(uint4*)(st + OBL + bo_ + v * 8) = vbl[v];
        }
    };

    auto comp = [&](int buf) {
        uint32_t st = smb + (uint32_t)(buf * STAGE) * 2;   // byte base
#pragma unroll
        for (int ch = 0; ch < 2; ch++) {
            uint32_t ah[2][4], al[2][4];
#pragma unroll
            for (int mi = 0; mi < 2; mi++) {
                uint32_t ar = (uint32_t)(wm + mi * 16 + (lane & 15));
                uint32_t ac = (uint32_t)(ch * 16 + ((lane >> 4) << 3));
                uint32_t aoff = (ar * ASTR + ac) * 2;
                ldm_x4(ah[mi], st + OAH * 2 + aoff);
                ldm_x4(al[mi], st + OAL * 2 + aoff);
            }
            uint32_t br = (uint32_t)(wn + (lane & 7) + ((lane & 16) >> 1));
            uint32_t bc = (uint32_t)(ch * 16 + (lane & 8));
#pragma unroll
            for (int njp = 0; njp < NJ / 2; njp++) {
                uint32_t boff = ((br + njp * 16) * ASTR + bc) * 2;
                uint32_t bh[4], bl[4];
                ldm_x4(bh, st + OBH * 2 + boff);
                ldm_x4(bl, st + OBL * 2 + boff);
#pragma unroll
                for (int mi = 0; mi < 2; mi++) {
                    mma16(c[mi][2 * njp], al[mi], bh[0], bh[1]);
                    mma16(c[mi][2 * njp], ah[mi], bl[0], bl[1]);
                    mma16(c[mi][2 * njp], ah[mi], bh[0], bh[1]);
                    mma16(c[mi][2 * njp + 1], al[mi], bh[2], bh[3]);
                    mma16(c[mi][2 * njp + 1], ah[mi], bl[2], bl[3]);
                    mma16(c[mi][2 * njp + 1], ah[mi], bh[2], bh[3]);
                }
            }
        }
    };

    const int T = K / BK;
    ldg(0);
    sts(0);
    __syncthreads();
    for (int kt = 0; kt < T; kt++) {
        if (kt + 1 < T) ldg(kt + 1);
        comp(kt & 1);
        if (kt + 1 < T) sts((kt + 1) & 1);
        __syncthreads();
    }

    // epilogue
#pragma unroll
    for (int mi = 0; mi < 2; mi++) {
#pragma unroll
        for (int nj = 0; nj < NJ; nj++) {
            int row0 = bm0 + wm + mi * 16 + (lane >> 2);
            int col = bn0 + wn + nj * 8 + (lane & 3) * 2;
            float v0 = c[mi][nj][0], v1 = c[mi][nj][1];
            float v2 = c[mi][nj][2], v3 = c[mi][nj][3];
            if (BIAS) {
                float bb0 = (col < Ntrue) ? bias[col] : 0.f;
                float bb1 = (col + 1 < Ntrue) ? bias[col + 1] : 0.f;
                v0 += bb0; v1 += bb1; v2 += bb0; v3 += bb1;
            }
            if (RELU) {
                v0 = fmaxf(v0, 0.f); v1 = fmaxf(v1, 0.f);
                v2 = fmaxf(v2, 0.f); v3 = fmaxf(v3, 0.f);
            }
            if (OUTP) {
                float h0, l0, h1, l1;
                if (row0 < M) {
                    split1(v0, h0, l0); split1(v1, h1, l1);
                    *(__nv_bfloat162*)(Chi + (size_t)row0 * Npad + col) = __floats2bfloat162_rn(h0, h1);
                    *(__nv_bfloat162*)(Clo + (size_t)row0 * Npad + col) = __floats2bfloat162_rn(l0, l1);
                }
                if (row0 + 8 < M) {
                    split1(v2, h0, l0); split1(v3, h1, l1);
                    *(__nv_bfloat162*)(Chi + (size_t)(row0 + 8) * Npad + col) = __floats2bfloat162_rn(h0, h1);
                    *(__nv_bfloat162*)(Clo + (size_t)(row0 + 8) * Npad + col) = __floats2bfloat162_rn(l0, l1);
                }
            } else {
                if (row0 < M)
                    *(float2*)&Cf[(size_t)row0 * Npad + col] = make_float2(v0, v1);
                if (row0 + 8 < M)
                    *(float2*)&Cf[(size_t)(row0 + 8) * Npad + col] = make_float2(v2, v3);
            }
        }
    }
}

// ---------------- GCN propagation: fp32 in, bf16 planes out --------------------
template <int C4>
__global__ void k_agg4p(const float* __restrict__ h,
                        __nv_bfloat16* __restrict__ phi, __nv_bfloat16* __restrict__ plo) {
    int v = blockIdx.x * 8 + (threadIdx.x >> 5);
    if (v >= NN) return;
    int lane = threadIdx.x & 31;
    constexpr int F = C4 * 128;
    float dv = g_dinv[v];
    const float4* hv = (const float4*)(h + (size_t)v * F);
    float4 acc[C4];
    float s2 = dv * dv;
#pragma unroll
    for (int i = 0; i < C4; i++) {
        float4 t = hv[lane + i * 32];
        acc[i] = make_float4(t.x * s2, t.y * s2, t.z * s2, t.w * s2);
    }
    int e = g_rowptr[v], end = g_rowptr[v + 1];
    for (; e < end; e++) {
        int s = g_colsrc[e];
        if ((unsigned)s >= NN) continue;
        float nrm = dv * g_dinv[s];
        const float4* hs = (const float4*)(h + (size_t)s * F);
#pragma unroll
        for (int i = 0; i < C4; i++) {
            float4 t = hs[lane + i * 32];
            acc[i].x += nrm * t.x; acc[i].y += nrm * t.y;
            acc[i].z += nrm * t.z; acc[i].w += nrm * t.w;
        }
    }
#pragma unroll
    for (int i = 0; i < C4; i++) {
        int base = 4 * (lane + i * 32);
        float hx, lx, hy, ly, hz, lz, hw, lw;
        split1(acc[i].x, hx, lx); split1(acc[i].y, hy, ly);
        split1(acc[i].z, hz, lz); split1(acc[i].w, hw, lw);
        *(__nv_bfloat162*)(phi + (size_t)v * F + base)     = __floats2bfloat162_rn(hx, hy);
        *(__nv_bfloat162*)(phi + (size_t)v * F + base + 2) = __floats2bfloat162_rn(hz, hw);
        *(__nv_bfloat162*)(plo + (size_t)v * F + base)     = __floats2bfloat162_rn(lx, ly);
        *(__nv_bfloat162*)(plo + (size_t)v * F + base + 2) = __floats2bfloat162_rn(lz, lw);
    }
}

// F = 64 fp32->fp32 variant (final layer)
__global__ void k_agg_f2(const float* __restrict__ h, float* __restrict__ p) {
    int v = blockIdx.x * 8 + (threadIdx.x >> 5);
    if (v >= NN) return;
    int lane = threadIdx.x & 31;
    float dv = g_dinv[v];
    float2 a = ((const float2*)(h + (size_t)v * 64))[lane];
    float s2 = dv * dv;
    a.x *= s2; a.y *= s2;
    int e = g_rowptr[v], end = g_rowptr[v + 1];
    for (; e < end; e++) {
        int s = g_colsrc[e];
        if ((unsigned)s >= NN) continue;
        float nrm = dv * g_dinv[s];
        float2 t = ((const float2*)(h + (size_t)s * 64))[lane];
        a.x += nrm * t.x; a.y += nrm * t.y;
    }
    ((float2*)(p + (size_t)v * 64))[lane] = a;
}

// ---------------- softmax over 50 logits (+ final bias) ------------------------
__global__ void k_softmax(const float* __restrict__ p, const float* __restrict__ b,
                          float* __restrict__ out) {
    int v = blockIdx.x * 8 + (threadIdx.x >> 5);
    if (v >= NN) return;
    int lane = threadIdx.x & 31;
    const float* pv = p + (size_t)v * 64;
    float v0 = pv[lane] + b[lane];
    bool has1 = (lane + 32) < 50;
    float v1 = has1 ? (pv[lane + 32] + b[lane + 32]) : -1e30f;
    float m = fmaxf(v0, v1);
#pragma unroll
    for (int off = 16; off >= 1; off >>= 1)
        m = fmaxf(m, __shfl_xor_sync(0xffffffffu, m, off));
    float e0 = __expf(v0 - m);
    float e1 = has1 ? __expf(v1 - m) : 0.f;
    float s = e0 + e1;
#pragma unroll
    for (int off = 16; off >= 1; off >>= 1)
        s += __shfl_xor_sync(0xffffffffu, s, off);
    float inv = 1.0f / s;
    out[(size_t)v * 50 + lane] = e0 * inv;
    if (has1) out[(size_t)v * 50 + lane + 32] = e1 * inv;
}

// ---------------- launch ------------------------------------------------------
static inline void* sym(const void* s) {
    void* p = nullptr;
    cudaGetSymbolAddress(&p, s);
    return p;
}

extern "C" void kernel_launch(void* const* d_in, const int* in_sizes, int n_in,
                              void* d_out, int out_size) {
    const float* x   = (const float*)d_in[0];
    const int*   ei  = (const int*)d_in[1];
    const float* w1  = (const float*)d_in[2];
    const float* b1  = (const float*)d_in[3];
    const float* w2  = (const float*)d_in[4];
    const float* b2  = (const float*)d_in[5];
    const float* w3  = (const float*)d_in[6];
    const float* b3  = (const float*)d_in[7];
    const float* g1w = (const float*)d_in[8];
    const float* g1b = (const float*)d_in[9];
    const float* g2w = (const float*)d_in[10];
    const float* g2b = (const float*)d_in[11];
    const float* g3w = (const float*)d_in[12];
    const float* g3b = (const float*)d_in[13];
    float* out = (float*)d_out;

    float* h128 = (float*)sym(g_h128);
    float* h256 = (float*)sym(g_h256);
    float* t64  = (float*)sym(g_t64);
    float* p64  = (float*)sym(g_p64);

    __nv_bfloat16* h32h = (__nv_bfloat16*)sym(g_h32h);
    __nv_bfloat16* h32l = (__nv_bfloat16*)sym(g_h32l);
    __nv_bfloat16* h64h = (__nv_bfloat16*)sym(g_h64h);
    __nv_bfloat16* h64l = (__nv_bfloat16*)sym(g_h64l);
    __nv_bfloat16* p128h = (__nv_bfloat16*)sym(g_p128h);
    __nv_bfloat16* p128l = (__nv_bfloat16*)sym(g_p128l);
    __nv_bfloat16* p256h = (__nv_bfloat16*)sym(g_p256h);
    __nv_bfloat16* p256l = (__nv_bfloat16*)sym(g_p256l);
    __nv_bfloat16* h512h = (__nv_bfloat16*)sym(g_h512h);
    __nv_bfloat16* h512l = (__nv_bfloat16*)sym(g_h512l);

    __nv_bfloat16* w2h = (__nv_bfloat16*)sym(g_w2h);
    __nv_bfloat16* w2l = (__nv_bfloat16*)sym(g_w2l);
    __nv_bfloat16* w3h = (__nv_bfloat16*)sym(g_w3h);
    __nv_bfloat16* w3l = (__nv_bfloat16*)sym(g_w3l);
    __nv_bfloat16* g1h = (__nv_bfloat16*)sym(g_g1h);
    __nv_bfloat16* g1l = (__nv_bfloat16*)sym(g_g1l);
    __nv_bfloat16* g2h = (__nv_bfloat16*)sym(g_g2h);
    __nv_bfloat16* g2l = (__nv_bfloat16*)sym(g_g2l);
    __nv_bfloat16* g3h = (__nv_bfloat16*)sym(g_g3h);
    __nv_bfloat16* g3l = (__nv_bfloat16*)sym(g_g3l);

    const int dyn128 = (2 * 128 * 40 + 2 * 128 * 40) * 2 * 2;  // 81920
    const int dyn64  = (2 * 128 * 40 + 2 * 64 * 40) * 2 * 2;   // 61440

    static cudaStream_t s1 = nullptr, s2 = nullptr;
    static cudaEvent_t eFork = nullptr, eCsr = nullptr, eWts = nullptr;
    static int init_done = 0;
    if (!init_done) {
        cudaFuncSetAttribute(k_gemm_bf<64, true, true, true>,
                             cudaFuncAttributeMaxDynamicSharedMemorySize, dyn64);
        cudaFuncSetAttribute(k_gemm_bf<128, true, true, false>,
                             cudaFuncAttributeMaxDynamicSharedMemorySize, dyn128);
        cudaFuncSetAttribute(k_gemm_bf<128, true, true, true>,
                             cudaFuncAttributeMaxDynamicSharedMemorySize, dyn128);
        cudaFuncSetAttribute(k_gemm_bf<64, false, false, false>,
                             cudaFuncAttributeMaxDynamicSharedMemorySize, dyn64);
        cudaStreamCreateWithFlags(&s1, cudaStreamNonBlocking);
        cudaStreamCreateWithFlags(&s2, cudaStreamNonBlocking);
        cudaEventCreateWithFlags(&eFork, cudaEventDisableTiming);
        cudaEventCreateWithFlags(&eCsr, cudaEventDisableTiming);
        cudaEventCreateWithFlags(&eWts, cudaEventDisableTiming);
        init_done = 1;
    }

    // fork: CSR build on s1, big weight splits on s2, MLP chain on default
    cudaEventRecord(eFork, 0);
    cudaStreamWaitEvent(s1, eFork, 0);
    cudaStreamWaitEvent(s2, eFork, 0);

    // s1: degree + CSR
    k_zero_cnt<<<(NN + 255) / 256, 256, 0, s1>>>();
    k_count<<<(NE + 255) / 256, 256, 0, s1>>>(ei);
    k_scan1<<<NBLK, 1024, 0, s1>>>();
    k_scan2<<<1, 64, 0, s1>>>();
    k_scan3<<<(NN + 255) / 256, 256, 0, s1>>>();
    k_scatter<<<(NE + 255) / 256, 256, 0, s1>>>(ei);
    cudaEventRecord(eCsr, s1);

    // s2: GCN weight splits
    k_split_t<<<(128 * 256 + 255) / 256, 256, 0, s2>>>(g1w, g1h, g1l, 128, 256);
    k_split_t<<<(256 * 512 + 255) / 256, 256, 0, s2>>>(g2w, g2h, g2l, 256, 512);
    k_split_t<<<(512 * 50 + 255) / 256, 256, 0, s2>>>(g3w, g3h, g3l, 512, 50);
    cudaEventRecord(eWts, s2);

    // default: MLP weight splits + MLP chain
    k_split_t<<<(32 * 64 + 255) / 256, 256>>>(w2, w2h, w2l, 32, 64);
    k_split_t<<<(64 * 128 + 255) / 256, 256>>>(w3, w3h, w3l, 64, 128);

    const int MB = (NN + 127) / 128;   // 391

    k_mlp1<<<(NN + 255) / 256, 256>>>(x, w1, b1, h32h, h32l);
    k_gemm_bf<64, true, true, true><<<dim3(MB, 1), 256, dyn64>>>(
        h32h, h32l, w2h, w2l, b2, nullptr, h64h, h64l, NN, 32, 64, 64);
    k_gemm_bf<128, true, true, false><<<dim3(MB, 1), 256, dyn128>>>(
        h64h, h64l, w3h, w3l, b3, h128, nullptr, nullptr, NN, 64, 128, 128);

    // join: aggregation needs CSR; GCN GEMMs need weight planes
    cudaStreamWaitEvent(0, eCsr, 0);
    cudaStreamWaitEvent(0, eWts, 0);

    // GCN1: propagate at 128 (planes out), then 128->256 fp32 out
    k_agg4p<1><<<(NN + 7) / 8, 256>>>(h128, p128h, p128l);
    k_gemm_bf<128, true, true, false><<<dim3(MB, 2), 256, dyn128>>>(
        p128h, p128l, g1h, g1l, g1b, h256, nullptr, nullptr, NN, 128, 256, 256);

    // GCN2: propagate at 256 (planes out), then 256->512 planes out
    k_agg4p<2><<<(NN + 7) / 8, 256>>>(h256, p256h, p256l);
    k_gemm_bf<128, true, true, true><<<dim3(MB, 4), 256, dyn128>>>(
        p256h, p256l, g2h, g2l, g2b, nullptr, h512h, h512l, NN, 256, 512, 512);

    // GCN3: 512->50 (pad 64, bias deferred), fp32 out, then propagate at 64
    k_gemm_bf<64, false, false, false><<<dim3(MB, 1), 256, dyn64>>>(
        h512h, h512l, g3h, g3l, nullptr, t64, nullptr, nullptr, NN, 512, 50, 64);
    k_agg_f2<<<(NN + 7) / 8, 256>>>(t64, p64);

    // softmax(p + g3b)
    k_softmax<<<(NN + 7) / 8, 256>>>(p64, g3b, out);
}

// round 8
// speedup vs baseline: 2.3926x; 1.1320x over previous
#include <cuda_runtime.h>
#include <cuda_bf16.h>
#include <math.h>
#include <stdint.h>

#define NN 50000
#define NE 800000
#define NBLK ((NN + 1023) / 1024)

// ---------------- scratch (static device globals; no allocation) -------------
__device__ int   g_cnt[NN];
__device__ int   g_rowptr[NN + 1];
__device__ int   g_cursor[NN];
__device__ int   g_colsrc[NE];
__device__ int   g_bsum[64];
__device__ float g_dinv[NN];

__device__ float g_h128[(size_t)NN * 128];
__device__ float g_h256[(size_t)NN * 256];
__device__ float g_t64 [(size_t)NN * 64];

__device__ __align__(256) __nv_bfloat16 g_h32h [(size_t)NN * 32],  g_h32l [(size_t)NN * 32];
__device__ __align__(256) __nv_bfloat16 g_h64h [(size_t)NN * 64],  g_h64l [(size_t)NN * 64];
__device__ __align__(256) __nv_bfloat16 g_p128h[(size_t)NN * 128], g_p128l[(size_t)NN * 128];
__device__ __align__(256) __nv_bfloat16 g_p256h[(size_t)NN * 256], g_p256l[(size_t)NN * 256];
__device__ __align__(256) __nv_bfloat16 g_h512h[(size_t)NN * 512], g_h512l[(size_t)NN * 512];

__device__ __align__(256) __nv_bfloat16 g_w2h[64 * 32],   g_w2l[64 * 32];
__device__ __align__(256) __nv_bfloat16 g_w3h[128 * 64],  g_w3l[128 * 64];
__device__ __align__(256) __nv_bfloat16 g_g1h[256 * 128], g_g1l[256 * 128];
__device__ __align__(256) __nv_bfloat16 g_g2h[512 * 256], g_g2l[512 * 256];
__device__ __align__(256) __nv_bfloat16 g_g3h[50 * 512],  g_g3l[50 * 512];

// ---------------- helpers ------------------------------------------------------
__device__ __forceinline__ void split1(float x, float& hi, float& lo) {
    __nv_bfloat16 h = __float2bfloat16(x);
    hi = __bfloat162float(h);
    lo = x - hi;
}
__device__ __forceinline__ void mma16(float c[4], const uint32_t a[4], uint32_t b0, uint32_t b1) {
    asm("mma.sync.aligned.m16n8k16.row.col.f32.bf16.bf16.f32 "
        "{%0,%1,%2,%3},{%4,%5,%6,%7},{%8,%9},{%0,%1,%2,%3};"
        : "+f"(c[0]), "+f"(c[1]), "+f"(c[2]), "+f"(c[3])
        : "r"(a[0]), "r"(a[1]), "r"(a[2]), "r"(a[3]), "r"(b0), "r"(b1));
}
__device__ __forceinline__ void ldm_x4(uint32_t r[4], uint32_t saddr) {
    asm volatile("ldmatrix.sync.aligned.m8n8.x4.shared.b16 {%0,%1,%2,%3}, [%4];"
        : "=r"(r[0]), "=r"(r[1]), "=r"(r[2]), "=r"(r[3]) : "r"(saddr));
}
__device__ __forceinline__ uint32_t smem_u32(const void* p) {
    uint32_t a;
    asm("{ .reg .u64 t; cvta.to.shared.u64 t, %1; cvt.u32.u64 %0, t; }" : "=r"(a) : "l"(p));
    return a;
}
__device__ __forceinline__ void cpa16(uint32_t dst, const void* src, bool pred) {
    int sz = pred ? 16 : 0;
    asm volatile("cp.async.cg.shared.global [%0], [%1], 16, %2;"
        :: "r"(dst), "l"(src), "r"(sz));
}
#define CP_COMMIT() asm volatile("cp.async.commit_group;")
#define CP_WAIT0()  asm volatile("cp.async.wait_group 0;")

// ---------------- degree / CSR build -----------------------------------------
__global__ void k_zero_cnt() {
    int i = blockIdx.x * blockDim.x + threadIdx.x;
    if (i < NN) g_cnt[i] = 0;
}
__global__ void k_count(const int* __restrict__ ei) {
    int e = blockIdx.x * blockDim.x + threadIdx.x;
    if (e < NE) {
        int dst = ei[NE + e];
        if ((unsigned)dst < NN) atomicAdd(&g_cnt[dst], 1);
    }
}
__global__ void k_scan1() {
    __shared__ int sh[1024];
    int tid = threadIdx.x;
    int i = blockIdx.x * 1024 + tid;
    int v = (i < NN) ? g_cnt[i] : 0;
    if (i < NN) g_dinv[i] = rsqrtf((float)v + 1.0f);
    sh[tid] = v;
    __syncthreads();
    for (int off = 1; off < 1024; off <<= 1) {
        int t = (tid >= off) ? sh[tid - off] : 0;
        __syncthreads();
        sh[tid] += t;
        __syncthreads();
    }
    if (i < NN) g_rowptr[i] = sh[tid] - v;
    if (tid == 1023) g_bsum[blockIdx.x] = sh[1023];
}
__global__ void k_scan2() {
    __shared__ int sh[64];
    int tid = threadIdx.x;
    int v = (tid < NBLK) ? g_bsum[tid] : 0;
    sh[tid] = v;
    __syncthreads();
    for (int off = 1; off < 64; off <<= 1) {
        int t = (tid >= off) ? sh[tid - off] : 0;
        __syncthreads();
        sh[tid] += t;
        __syncthreads();
    }
    g_bsum[tid] = sh[tid] - v;
}
__global__ void k_scan3() {
    int i = blockIdx.x * blockDim.x + threadIdx.x;
    if (i < NN) {
        int r = g_rowptr[i] + g_bsum[i >> 10];
        g_rowptr[i] = r;
        g_cursor[i] = r;
    }
    if (i == 0) g_rowptr[NN] = NE;
}
__global__ void k_scatter(const int* __restrict__ ei) {
    int e = blockIdx.x * blockDim.x + threadIdx.x;
    if (e < NE) {
        int dst = ei[NE + e];
        int src = ei[e];
        if ((unsigned)dst < NN && (unsigned)src < NN) {
            int pos = atomicAdd(&g_cursor[dst], 1);
            if ((unsigned)pos < NE) g_colsrc[pos] = src;
        }
    }
}

// ---------------- weight split + transpose -------------------------------------
__global__ void k_split_t(const float* __restrict__ src, __nv_bfloat16* __restrict__ hi,
                          __nv_bfloat16* __restrict__ lo, int K, int N) {
    int i = blockIdx.x * blockDim.x + threadIdx.x;
    if (i < K * N) {
        int k = i / N, n = i % N;
        float x = src[i];
        float h, l;
        split1(x, h, l);
        hi[(size_t)n * K + k] = __float2bfloat16(h);
        lo[(size_t)n * K + k] = __float2bfloat16(l);
    }
}

// ---------------- MLP layer 1 (K=3 -> 32), writes planes ----------------------
__global__ __launch_bounds__(256)
void k_mlp1(const float* __restrict__ x, const float* __restrict__ w,
            const float* __restrict__ b,
            __nv_bfloat16* __restrict__ hh, __nv_bfloat16* __restrict__ hl) {
    __shared__ float sw[96], sb[32];
    int tid = threadIdx.x;
    if (tid < 96) sw[tid] = w[tid];
    if (tid < 32) sb[tid] = b[tid];
    __syncthreads();
    int v = blockIdx.x * 256 + tid;
    if (v >= NN) return;
    float x0 = x[3 * v], x1 = x[3 * v + 1], x2 = x[3 * v + 2];
    __nv_bfloat162* ph = (__nv_bfloat162*)(hh + (size_t)v * 32);
    __nv_bfloat162* pl = (__nv_bfloat162*)(hl + (size_t)v * 32);
#pragma unroll
    for (int j = 0; j < 32; j += 2) {
        float h0 = fmaxf(x0 * sw[j] + x1 * sw[32 + j] + x2 * sw[64 + j] + sb[j], 0.f);
        float h1 = fmaxf(x0 * sw[j + 1] + x1 * sw[32 + j + 1] + x2 * sw[64 + j + 1] + sb[j + 1], 0.f);
        float a0, l0, a1, l1;
        split1(h0, a0, l0);
        split1(h1, a1, l1);
        ph[j >> 1] = __floats2bfloat162_rn(a0, a1);
        pl[j >> 1] = __floats2bfloat162_rn(l0, l1);
    }
}

// ---------------- bf16x3 tensor-core GEMM (cp.async staging) -------------------
template <int BN, bool RELU, bool BIAS, bool OUTP>
__global__ __launch_bounds__(256)
void k_gemm_bf(const __nv_bfloat16* __restrict__ Ahi, const __nv_bfloat16* __restrict__ Alo,
               const __nv_bfloat16* __restrict__ Whi, const __nv_bfloat16* __restrict__ Wlo,
               const float* __restrict__ bias,
               float* __restrict__ Cf,
               __nv_bfloat16* __restrict__ Chi, __nv_bfloat16* __restrict__ Clo,
               int M, int K, int Ntrue, int Npad) {
    constexpr int BM = 128, BK = 32, ASTR = 40;
    constexpr int A_H = BM * ASTR;
    constexpr int B_H = BN * ASTR;
    constexpr int STAGE = 2 * A_H + 2 * B_H;
    constexpr int OAH = 0, OAL = A_H, OBH = 2 * A_H, OBL = 2 * A_H + B_H;
    constexpr int NJ = (BN / 2) / 8;
    constexpr int TPN = 256 / BN;
    constexpr int KSEG = BK / TPN;
    constexpr int NV = KSEG / 8;

    extern __shared__ __nv_bfloat16 sm[];
    const uint32_t smb = smem_u32(sm);
    int tid = threadIdx.x, lane = tid & 31, wid = tid >> 5;
    int wm = (wid & 3) * 32, wn = (wid >> 2) * (BN / 2);
    int bm0 = blockIdx.x * BM, bn0 = blockIdx.y * BN;

    float c[2][NJ][4];
#pragma unroll
    for (int mi = 0; mi < 2; mi++)
#pragma unroll
        for (int nj = 0; nj < NJ; nj++)
#pragma unroll
            for (int r = 0; r < 4; r++) c[mi][nj][r] = 0.f;

    int arow = tid >> 1, ahalf = tid & 1;
    int brow = tid / TPN, bseg = tid % TPN;
    bool aok = (bm0 + arow) < M;
    bool bok = (bn0 + brow) < Ntrue;
    const __nv_bfloat16* pAh = Ahi + (size_t)(bm0 + arow) * K + ahalf * 16;
    const __nv_bfloat16* pAl = Alo + (size_t)(bm0 + arow) * K + ahalf * 16;
    const __nv_bfloat16* pBh = Whi + (size_t)(bn0 + brow) * K + bseg * KSEG;
    const __nv_bfloat16* pBl = Wlo + (size_t)(bn0 + brow) * K + bseg * KSEG;
    uint32_t dA = smb + ((uint32_t)arow * ASTR + ahalf * 16) * 2;
    uint32_t dB = smb + ((uint32_t)brow * ASTR + bseg * KSEG) * 2;

    auto stage_in = [&](int kt) {
        int k0 = kt * BK;
        uint32_t so = (uint32_t)((kt & 1) * STAGE) * 2;
        cpa16(so + dA + OAH * 2,      pAh + k0,     aok);
        cpa16(so + dA + OAH * 2 + 16, pAh + k0 + 8, aok);
        cpa16(so + dA + OAL * 2,      pAl + k0,     aok);
        cpa16(so + dA + OAL * 2 + 16, pAl + k0 + 8, aok);
#pragma unroll
        for (int v = 0; v < NV; v++) {
            cpa16(so + dB + OBH * 2 + v * 16, pBh + k0 + v * 8, bok);
            cpa16(so + dB + OBL * 2 + v * 16, pBl + k0 + v * 8, bok);
        }
        CP_COMMIT();
    };

    auto comp = [&](int buf) {
        uint32_t st = smb + (uint32_t)(buf * STAGE) * 2;
#pragma unroll
        for (int ch = 0; ch < 2; ch++) {
            uint32_t ah[2][4], al[2][4];
#pragma unroll
            for (int mi = 0; mi < 2; mi++) {
                uint32_t ar = (uint32_t)(wm + mi * 16 + (lane & 15));
                uint32_t ac = (uint32_t)(ch * 16 + ((lane >> 4) << 3));
                uint32_t aoff = (ar * ASTR + ac) * 2;
                ldm_x4(ah[mi], st + OAH * 2 + aoff);
                ldm_x4(al[mi], st + OAL * 2 + aoff);
            }
            uint32_t br = (uint32_t)(wn + (lane & 7) + ((lane & 16) >> 1));
            uint32_t bc = (uint32_t)(ch * 16 + (lane & 8));
#pragma unroll
            for (int njp = 0; njp < NJ / 2; njp++) {
                uint32_t boff = ((br + njp * 16) * ASTR + bc) * 2;
                uint32_t bh[4], bl[4];
                ldm_x4(bh, st + OBH * 2 + boff);
                ldm_x4(bl, st + OBL * 2 + boff);
#pragma unroll
                for (int mi = 0; mi < 2; mi++) {
                    mma16(c[mi][2 * njp], al[mi], bh[0], bh[1]);
                    mma16(c[mi][2 * njp], ah[mi], bl[0], bl[1]);
                    mma16(c[mi][2 * njp], ah[mi], bh[0], bh[1]);
                    mma16(c[mi][2 * njp + 1], al[mi], bh[2], bh[3]);
                    mma16(c[mi][2 * njp + 1], ah[mi], bl[2], bl[3]);
                    mma16(c[mi][2 * njp + 1], ah[mi], bh[2], bh[3]);
                }
            }
        }
    };

    const int T = K / BK;
    stage_in(0);
    for (int kt = 0; kt < T; kt++) {
        CP_WAIT0();
        __syncthreads();
        if (kt + 1 < T) stage_in(kt + 1);
        comp(kt & 1);
        __syncthreads();
    }

    // epilogue
#pragma unroll
    for (int mi = 0; mi < 2; mi++) {
#pragma unroll
        for (int nj = 0; nj < NJ; nj++) {
            int row0 = bm0 + wm + mi * 16 + (lane >> 2);
            int col = bn0 + wn + nj * 8 + (lane & 3) * 2;
            float v0 = c[mi][nj][0], v1 = c[mi][nj][1];
            float v2 = c[mi][nj][2], v3 = c[mi][nj][3];
            if (BIAS) {
                float bb0 = (col < Ntrue) ? bias[col] : 0.f;
                float bb1 = (col + 1 < Ntrue) ? bias[col + 1] : 0.f;
                v0 += bb0; v1 += bb1; v2 += bb0; v3 += bb1;
            }
            if (RELU) {
                v0 = fmaxf(v0, 0.f); v1 = fmaxf(v1, 0.f);
                v2 = fmaxf(v2, 0.f); v3 = fmaxf(v3, 0.f);
            }
            if (OUTP) {
                float h0, l0, h1, l1;
                if (row0 < M) {
                    split1(v0, h0, l0); split1(v1, h1, l1);
                    *(__nv_bfloat162*)(Chi + (size_t)row0 * Npad + col) = __floats2bfloat162_rn(h0, h1);
                    *(__nv_bfloat162*)(Clo + (size_t)row0 * Npad + col) = __floats2bfloat162_rn(l0, l1);
                }
                if (row0 + 8 < M) {
                    split1(v2, h0, l0); split1(v3, h1, l1);
                    *(__nv_bfloat162*)(Chi + (size_t)(row0 + 8) * Npad + col) = __floats2bfloat162_rn(h0, h1);
                    *(__nv_bfloat162*)(Clo + (size_t)(row0 + 8) * Npad + col) = __floats2bfloat162_rn(l0, l1);
                }
            } else {
                if (row0 < M)
                    *(float2*)&Cf[(size_t)row0 * Npad + col] = make_float2(v0, v1);
                if (row0 + 8 < M)
                    *(float2*)&Cf[(size_t)(row0 + 8) * Npad + col] = make_float2(v2, v3);
            }
        }
    }
}

// ---------------- GCN propagation: fp32 in, bf16 planes out --------------------
template <int C4>
__global__ void k_agg4p(const float* __restrict__ h,
                        __nv_bfloat16* __restrict__ phi, __nv_bfloat16* __restrict__ plo) {
    int v = blockIdx.x * 8 + (threadIdx.x >> 5);
    if (v >= NN) return;
    int lane = threadIdx.x & 31;
    constexpr int F = C4 * 128;
    float dv = g_dinv[v];
    const float4* hv = (const float4*)(h + (size_t)v * F);
    float4 acc[C4];
    float s2 = dv * dv;
#pragma unroll
    for (int i = 0; i < C4; i++) {
        float4 t = hv[lane + i * 32];
        acc[i] = make_float4(t.x * s2, t.y * s2, t.z * s2, t.w * s2);
    }
    int e = g_rowptr[v], end = g_rowptr[v + 1];
    for (; e < end; e++) {
        int s = g_colsrc[e];
        if ((unsigned)s >= NN) continue;
        float nrm = dv * g_dinv[s];
        const float4* hs = (const float4*)(h + (size_t)s * F);
#pragma unroll
        for (int i = 0; i < C4; i++) {
            float4 t = hs[lane + i * 32];
            acc[i].x += nrm * t.x; acc[i].y += nrm * t.y;
            acc[i].z += nrm * t.z; acc[i].w += nrm * t.w;
        }
    }
#pragma unroll
    for (int i = 0; i < C4; i++) {
        int base = 4 * (lane + i * 32);
        float hx, lx, hy, ly, hz, lz, hw, lw;
        split1(acc[i].x, hx, lx); split1(acc[i].y, hy, ly);
        split1(acc[i].z, hz, lz); split1(acc[i].w, hw, lw);
        *(__nv_bfloat162*)(phi + (size_t)v * F + base)     = __floats2bfloat162_rn(hx, hy);
        *(__nv_bfloat162*)(phi + (size_t)v * F + base + 2) = __floats2bfloat162_rn(hz, hw);
        *(__nv_bfloat162*)(plo + (size_t)v * F + base)     = __floats2bfloat162_rn(lx, ly);
        *(__nv_bfloat162*)(plo + (size_t)v * F + base + 2) = __floats2bfloat162_rn(lz, lw);
    }
}

// ---------------- fused final aggregation + bias + softmax ---------------------
// t64 rows: cols 0..49 logits (pre-propagation), 50..63 zero.
__global__ void k_agg_soft(const float* __restrict__ h, const float* __restrict__ b,
                           float* __restrict__ out) {
    int v = blockIdx.x * 8 + (threadIdx.x >> 5);
    if (v >= NN) return;
    int lane = threadIdx.x & 31;
    float dv = g_dinv[v];
    float2 a = ((const float2*)(h + (size_t)v * 64))[lane];
    float s2 = dv * dv;
    a.x *= s2; a.y *= s2;
    int e = g_rowptr[v], end = g_rowptr[v + 1];
    for (; e < end; e++) {
        int s = g_colsrc[e];
        if ((unsigned)s >= NN) continue;
        float nrm = dv * g_dinv[s];
        float2 t = ((const float2*)(h + (size_t)s * 64))[lane];
        a.x += nrm * t.x; a.y += nrm * t.y;
    }
    // softmax over cols {2*lane, 2*lane+1}, valid < 50
    int c0 = 2 * lane, c1 = 2 * lane + 1;
    float v0 = (c0 < 50) ? (a.x + b[c0]) : -1e30f;
    float v1 = (c1 < 50) ? (a.y + b[c1]) : -1e30f;
    float m = fmaxf(v0, v1);
#pragma unroll
    for (int off = 16; off >= 1; off >>= 1)
        m = fmaxf(m, __shfl_xor_sync(0xffffffffu, m, off));
    float e0 = (c0 < 50) ? __expf(v0 - m) : 0.f;
    float e1 = (c1 < 50) ? __expf(v1 - m) : 0.f;
    float s = e0 + e1;
#pragma unroll
    for (int off = 16; off >= 1; off >>= 1)
        s += __shfl_xor_sync(0xffffffffu, s, off);
    float inv = 1.0f / s;
    if (c0 < 50) out[(size_t)v * 50 + c0] = e0 * inv;
    if (c1 < 50) out[(size_t)v * 50 + c1] = e1 * inv;
}

// ---------------- launch ------------------------------------------------------
static inline void* sym(const void* s) {
    void* p = nullptr;
    cudaGetSymbolAddress(&p, s);
    return p;
}

extern "C" void kernel_launch(void* const* d_in, const int* in_sizes, int n_in,
                              void* d_out, int out_size) {
    const float* x   = (const float*)d_in[0];
    const int*   ei  = (const int*)d_in[1];
    const float* w1  = (const float*)d_in[2];
    const float* b1  = (const float*)d_in[3];
    const float* w2  = (const float*)d_in[4];
    const float* b2  = (const float*)d_in[5];
    const float* w3  = (const float*)d_in[6];
    const float* b3  = (const float*)d_in[7];
    const float* g1w = (const float*)d_in[8];
    const float* g1b = (const float*)d_in[9];
    const float* g2w = (const float*)d_in[10];
    const float* g2b = (const float*)d_in[11];
    const float* g3w = (const float*)d_in[12];
    const float* g3b = (const float*)d_in[13];
    float* out = (float*)d_out;

    float* h128 = (float*)sym(g_h128);
    float* h256 = (float*)sym(g_h256);
    float* t64  = (float*)sym(g_t64);

    __nv_bfloat16* h32h = (__nv_bfloat16*)sym(g_h32h);
    __nv_bfloat16* h32l = (__nv_bfloat16*)sym(g_h32l);
    __nv_bfloat16* h64h = (__nv_bfloat16*)sym(g_h64h);
    __nv_bfloat16* h64l = (__nv_bfloat16*)sym(g_h64l);
    __nv_bfloat16* p128h = (__nv_bfloat16*)sym(g_p128h);
    __nv_bfloat16* p128l = (__nv_bfloat16*)sym(g_p128l);
    __nv_bfloat16* p256h = (__nv_bfloat16*)sym(g_p256h);
    __nv_bfloat16* p256l = (__nv_bfloat16*)sym(g_p256l);
    __nv_bfloat16* h512h = (__nv_bfloat16*)sym(g_h512h);
    __nv_bfloat16* h512l = (__nv_bfloat16*)sym(g_h512l);

    __nv_bfloat16* w2h = (__nv_bfloat16*)sym(g_w2h);
    __nv_bfloat16* w2l = (__nv_bfloat16*)sym(g_w2l);
    __nv_bfloat16* w3h = (__nv_bfloat16*)sym(g_w3h);
    __nv_bfloat16* w3l = (__nv_bfloat16*)sym(g_w3l);
    __nv_bfloat16* g1h = (__nv_bfloat16*)sym(g_g1h);
    __nv_bfloat16* g1l = (__nv_bfloat16*)sym(g_g1l);
    __nv_bfloat16* g2h = (__nv_bfloat16*)sym(g_g2h);
    __nv_bfloat16* g2l = (__nv_bfloat16*)sym(g_g2l);
    __nv_bfloat16* g3h = (__nv_bfloat16*)sym(g_g3h);
    __nv_bfloat16* g3l = (__nv_bfloat16*)sym(g_g3l);

    const int dyn128 = (2 * 128 * 40 + 2 * 128 * 40) * 2 * 2;  // 81920
    const int dyn64  = (2 * 128 * 40 + 2 * 64 * 40) * 2 * 2;   // 61440

    static cudaStream_t s1 = nullptr, s2 = nullptr;
    static cudaEvent_t eFork = nullptr, eCsr = nullptr, eWts = nullptr;
    static int init_done = 0;
    if (!init_done) {
        cudaFuncSetAttribute(k_gemm_bf<64, true, true, true>,
                             cudaFuncAttributeMaxDynamicSharedMemorySize, dyn64);
        cudaFuncSetAttribute(k_gemm_bf<128, true, true, false>,
                             cudaFuncAttributeMaxDynamicSharedMemorySize, dyn128);
        cudaFuncSetAttribute(k_gemm_bf<128, true, true, true>,
                             cudaFuncAttributeMaxDynamicSharedMemorySize, dyn128);
        cudaFuncSetAttribute(k_gemm_bf<64, false, false, false>,
                             cudaFuncAttributeMaxDynamicSharedMemorySize, dyn64);
        cudaStreamCreateWithFlags(&s1, cudaStreamNonBlocking);
        cudaStreamCreateWithFlags(&s2, cudaStreamNonBlocking);
        cudaEventCreateWithFlags(&eFork, cudaEventDisableTiming);
        cudaEventCreateWithFlags(&eCsr, cudaEventDisableTiming);
        cudaEventCreateWithFlags(&eWts, cudaEventDisableTiming);
        init_done = 1;
    }

    cudaEventRecord(eFork, 0);
    cudaStreamWaitEvent(s1, eFork, 0);
    cudaStreamWaitEvent(s2, eFork, 0);

    // s1: degree + CSR
    k_zero_cnt<<<(NN + 255) / 256, 256, 0, s1>>>();
    k_count<<<(NE + 255) / 256, 256, 0, s1>>>(ei);
    k_scan1<<<NBLK, 1024, 0, s1>>>();
    k_scan2<<<1, 64, 0, s1>>>();
    k_scan3<<<(NN + 255) / 256, 256, 0, s1>>>();
    k_scatter<<<(NE + 255) / 256, 256, 0, s1>>>(ei);
    cudaEventRecord(eCsr, s1);

    // s2: GCN weight splits
    k_split_t<<<(128 * 256 + 255) / 256, 256, 0, s2>>>(g1w, g1h, g1l, 128, 256);
    k_split_t<<<(256 * 512 + 255) / 256, 256, 0, s2>>>(g2w, g2h, g2l, 256, 512);
    k_split_t<<<(512 * 50 + 255) / 256, 256, 0, s2>>>(g3w, g3h, g3l, 512, 50);
    cudaEventRecord(eWts, s2);

    // default: MLP weight splits + MLP chain
    k_split_t<<<(32 * 64 + 255) / 256, 256>>>(w2, w2h, w2l, 32, 64);
    k_split_t<<<(64 * 128 + 255) / 256, 256>>>(w3, w3h, w3l, 64, 128);

    const int MB = (NN + 127) / 128;   // 391

    k_mlp1<<<(NN + 255) / 256, 256>>>(x, w1, b1, h32h, h32l);
    k_gemm_bf<64, true, true, true><<<dim3(MB, 1), 256, dyn64>>>(
        h32h, h32l, w2h, w2l, b2, nullptr, h64h, h64l, NN, 32, 64, 64);
    k_gemm_bf<128, true, true, false><<<dim3(MB, 1), 256, dyn128>>>(
        h64h, h64l, w3h, w3l, b3, h128, nullptr, nullptr, NN, 64, 128, 128);

    cudaStreamWaitEvent(0, eCsr, 0);
    cudaStreamWaitEvent(0, eWts, 0);

    // GCN1
    k_agg4p<1><<<(NN + 7) / 8, 256>>>(h128, p128h, p128l);
    k_gemm_bf<128, true, true, false><<<dim3(MB, 2), 256, dyn128>>>(
        p128h, p128l, g1h, g1l, g1b, h256, nullptr, nullptr, NN, 128, 256, 256);

    // GCN2
    k_agg4p<2><<<(NN + 7) / 8, 256>>>(h256, p256h, p256l);
    k_gemm_bf<128, true, true, true><<<dim3(MB, 4), 256, dyn128>>>(
        p256h, p256l, g2h, g2l, g2b, nullptr, h512h, h512l, NN, 256, 512, 512);

    // GCN3: 512->50 (pad 64), then fused propagate+softmax
    k_gemm_bf<64, false, false, false><<<dim3(MB, 1), 256, dyn64>>>(
        h512h, h512l, g3h, g3l, nullptr, t64, nullptr, nullptr, NN, 512, 50, 64);
    k_agg_soft<<<(NN + 7) / 8, 256>>>(t64, g3b, out);
}